// round 10
// baseline (speedup 1.0000x reference)
#include <cuda_runtime.h>
#include <math.h>
#include <stdint.h>

#define B_   32
#define L_   256
#define DM_  512
#define FF_  2048
#define E_   8
#define NPAIR 64

// ---------------- device scratch (static = allocation-free) ----------------
__device__ int   g_pair_e[NPAIR];
__device__ float g_pair_g[NPAIR];
// int8 limb planes: row = [a0 (K bytes) | a1 (K bytes)]
__device__ __align__(256) uint32_t g_xq [(size_t)8192  * 256];   // x rows, K=512
__device__ __align__(256) float    g_xs [8192];
__device__ __align__(256) float    g_w1tf[(size_t)E_ * FF_ * DM_]; // W1^T fp32
__device__ __align__(256) uint32_t g_w1q[(size_t)16384 * 256];   // K=512
__device__ __align__(256) float    g_w1s[16384];
__device__ __align__(256) float    g_w2tf[(size_t)E_ * DM_ * FF_]; // W2^T fp32
__device__ __align__(256) uint32_t g_w2q[(size_t)4096 * 1024];   // K=2048
__device__ __align__(256) float    g_w2s[4096];
__device__ __align__(256) float    g_gh [(size_t)NPAIR * L_ * FF_];   // g*gelu(h) fp32
__device__ __align__(256) uint32_t g_ghq[(size_t)16384 * 1024];  // K=2048
__device__ __align__(256) float    g_ghs[16384];
__device__ __align__(256) float    g_part[(size_t)NPAIR * L_ * DM_]; // gemm2 partials

// ---------------- helpers ----------------
__device__ __forceinline__ uint32_t smem_u32(const void* p) {
    uint32_t a;
    asm("{ .reg .u64 t; cvta.to.shared.u64 t, %1; cvt.u32.u64 %0, t; }" : "=r"(a) : "l"(p));
    return a;
}
__device__ __forceinline__ void cp16(uint32_t dst, const void* src) {
    asm volatile("cp.async.cg.shared.global [%0], [%1], 16;" :: "r"(dst), "l"(src));
}
#define CP_COMMIT() asm volatile("cp.async.commit_group;" ::: "memory")

__device__ __forceinline__ void ldsm_x4(uint32_t& r0, uint32_t& r1, uint32_t& r2, uint32_t& r3, uint32_t a) {
    asm volatile("ldmatrix.sync.aligned.m8n8.x4.shared.b16 {%0,%1,%2,%3}, [%4];"
                 : "=r"(r0), "=r"(r1), "=r"(r2), "=r"(r3) : "r"(a));
}
__device__ __forceinline__ void mma_s8(int* c, const uint32_t* a, uint32_t b0, uint32_t b1) {
    asm volatile("mma.sync.aligned.m16n8k32.row.col.s32.s8.s8.s32 "
                 "{%0,%1,%2,%3}, {%4,%5,%6,%7}, {%8,%9}, {%0,%1,%2,%3};"
                 : "+r"(c[0]), "+r"(c[1]), "+r"(c[2]), "+r"(c[3])
                 : "r"(a[0]), "r"(a[1]), "r"(a[2]), "r"(a[3]), "r"(b0), "r"(b1));
}
__device__ __forceinline__ float gelu_exact(float x) {
    return 0.5f * x * (1.0f + erff(x * 0.70710678118654752440f));
}

// Load a ROWS x 128-byte tile (XOR swizzle chunk^=(row&7)) via cp.async.
template<int ROWS, int NT>
__device__ __forceinline__ void load_tile_b(uint32_t dst, const uint8_t* src, int ldB, int tid) {
    constexpr int ITER = ROWS * 8 / NT;
#pragma unroll
    for (int j = 0; j < ITER; j++) {
        int idx = tid + j * NT;
        int r = idx >> 3, c = idx & 7;
        uint32_t off = (uint32_t)(r * 128 + ((c ^ (r & 7)) * 16));
        cp16(dst + off, src + (size_t)r * ldB + c * 16);
    }
}

// One 128-byte K chunk (4 k32 steps) of int8 limb MMAs over warp tile (MF*16)x(NF*8).
// acc0 += a0*b0 ; acc1 += a0*b1 + a1*b0.
template<int MF, int NF>
__device__ __forceinline__ void compute_i8(int (&acc0)[MF][NF][4], int (&acc1)[MF][NF][4],
                                           uint32_t aA, uint32_t aL,
                                           uint32_t bA, uint32_t bL,
                                           int wm, int wn, int lane) {
#pragma unroll
    for (int ks = 0; ks < 4; ks++) {
        uint32_t a0f[MF][4], a1f[MF][4];
#pragma unroll
        for (int mf = 0; mf < MF; mf++) {
            int r = wm + mf * 16 + (lane & 15);
            int c = ks * 2 + (lane >> 4);
            uint32_t off = (uint32_t)(r * 128 + ((c ^ (r & 7)) * 16));
            ldsm_x4(a0f[mf][0], a0f[mf][1], a0f[mf][2], a0f[mf][3], aA + off);
            ldsm_x4(a1f[mf][0], a1f[mf][1], a1f[mf][2], a1f[mf][3], aL + off);
        }
#pragma unroll
        for (int nfp = 0; nfp < NF / 2; nfp++) {
            int q = lane >> 3;
            int r = wn + (nfp * 2 + (q >> 1)) * 8 + (lane & 7);
            int c = ks * 2 + (q & 1);
            uint32_t off = (uint32_t)(r * 128 + ((c ^ (r & 7)) * 16));
            uint32_t b00, b01, b02, b03, b10, b11, b12, b13;
            ldsm_x4(b00, b01, b02, b03, bA + off);
            ldsm_x4(b10, b11, b12, b13, bL + off);
#pragma unroll
            for (int mf = 0; mf < MF; mf++) {
                mma_s8(acc0[mf][2 * nfp],     a0f[mf], b00, b01);
                mma_s8(acc0[mf][2 * nfp + 1], a0f[mf], b02, b03);
                mma_s8(acc1[mf][2 * nfp],     a0f[mf], b10, b11);
                mma_s8(acc1[mf][2 * nfp + 1], a0f[mf], b12, b13);
                mma_s8(acc1[mf][2 * nfp],     a1f[mf], b00, b01);
                mma_s8(acc1[mf][2 * nfp + 1], a1f[mf], b02, b03);
            }
        }
    }
}

// ---------------------------------------------------------------------------
// prep: gates + fp32 transposes of W1, W2 (device-symbol writes from device)
// ---------------------------------------------------------------------------
__device__ __forceinline__ void transpose_f(const float* __restrict__ W, float* __restrict__ T,
                                            int K, int N, int bx, int by, int bz,
                                            int tx, int ty, float (*s)[33]) {
    int n0 = bx * 32, k0 = by * 32;
    const float* Wp = W + (size_t)bz * K * N;
#pragma unroll
    for (int i = 0; i < 32; i += 8)
        s[ty + i][tx] = Wp[(size_t)(k0 + ty + i) * N + n0 + tx];
    __syncthreads();
#pragma unroll
    for (int i = 0; i < 32; i += 8)
        T[((size_t)bz * N + n0 + ty + i) * K + k0 + tx] = s[tx][ty + i];
}

__global__ void prep_kernel(const float* __restrict__ logits,
                            const int*   __restrict__ masks,
                            const float* __restrict__ W1,
                            const float* __restrict__ W2) {
    __shared__ float s[32][33];
    const int blk = blockIdx.x;
    const int tid = threadIdx.x;
    const int tx = tid & 31, ty = tid >> 5;

    if (blk < 8192) {                          // W1: [512][2048] -> [2048][512]
        transpose_f(W1, g_w1tf, DM_, FF_, blk & 63, (blk >> 6) & 15, blk >> 10, tx, ty, s);
    } else if (blk < 16384) {                  // W2: [2048][512] -> [512][2048]
        int i = blk - 8192;
        transpose_f(W2, g_w2tf, FF_, DM_, i & 15, (i >> 4) & 63, i >> 10, tx, ty, s);
    } else {
        int b = tid;
        if (b >= B_) return;
        float p[E_];
        float mx = -1e30f;
#pragma unroll
        for (int i = 0; i < E_; i++) { p[i] = logits[b * E_ + i]; mx = fmaxf(mx, p[i]); }
        float sum = 0.0f;
#pragma unroll
        for (int i = 0; i < E_; i++) { p[i] = expf(p[i] - mx); sum += p[i]; }
        float inv = 1.0f / sum;
#pragma unroll
        for (int i = 0; i < E_; i++) p[i] = (masks[b * E_ + i] == 1) ? p[i] * inv : 0.0f;
        int i1 = 0;
#pragma unroll
        for (int i = 1; i < E_; i++) if (p[i] > p[i1]) i1 = i;
        int i2 = -1;
#pragma unroll
        for (int i = 0; i < E_; i++) {
            if (i == i1) continue;
            if (i2 < 0 || p[i] > p[i2]) i2 = i;
        }
        float denom = p[i1] + p[i2] + 1e-9f;
        g_pair_e[2 * b + 0] = i1;  g_pair_g[2 * b + 0] = p[i1] / denom;
        g_pair_e[2 * b + 1] = i2;  g_pair_g[2 * b + 1] = p[i2] / denom;
    }
}

// ---------------------------------------------------------------------------
// rowquant: fp32 row -> per-row scale + 2 int8 limb planes. 1 warp / row.
// which: 0=x(ext), 1=w1tf, 2=w2tf, 3=gh
// ---------------------------------------------------------------------------
__device__ __forceinline__ int clamp127(int v) { return v < -127 ? -127 : (v > 127 ? 127 : v); }

__global__ void rq_kernel(int which, const float* __restrict__ xin) {
    const float* src; uint32_t* dst; float* sc; int K; int rows;
    if (which == 0)      { src = xin;    dst = g_xq;  sc = g_xs;  K = 512;  rows = 8192; }
    else if (which == 1) { src = g_w1tf; dst = g_w1q; sc = g_w1s; K = 512;  rows = 16384; }
    else if (which == 2) { src = g_w2tf; dst = g_w2q; sc = g_w2s; K = 2048; rows = 4096; }
    else                 { src = g_gh;   dst = g_ghq; sc = g_ghs; K = 2048; rows = 16384; }

    int w = blockIdx.x * 8 + (threadIdx.x >> 5);
    if (w >= rows) return;
    int lane = threadIdx.x & 31;
    const float4* s4 = (const float4*)(src + (size_t)w * K);
    int nt = K / 128;

    float m = 0.0f;
    for (int t = 0; t < nt; t++) {
        float4 v = s4[lane + 32 * t];
        m = fmaxf(m, fmaxf(fmaxf(fabsf(v.x), fabsf(v.y)), fmaxf(fabsf(v.z), fabsf(v.w))));
    }
#pragma unroll
    for (int o = 16; o > 0; o >>= 1)
        m = fmaxf(m, __shfl_xor_sync(0xFFFFFFFF, m, o));
    float s = (m > 0.0f) ? m * (1.0f / 127.0f) : 1.0f;
    float inv = 1.0f / s;

    uint32_t* d0 = dst + (size_t)w * (K / 2);
    uint32_t* d1 = d0 + K / 4;
    for (int t = 0; t < nt; t++) {
        float4 v = s4[lane + 32 * t];
        float vv[4] = {v.x, v.y, v.z, v.w};
        uint32_t p0 = 0, p1 = 0;
#pragma unroll
        for (int i = 0; i < 4; i++) {
            int a0 = clamp127(__float2int_rn(vv[i] * inv));
            float r = vv[i] - s * (float)a0;
            int a1 = clamp127(__float2int_rn(r * inv * 128.0f));
            p0 |= ((uint32_t)a0 & 0xFF) << (8 * i);
            p1 |= ((uint32_t)a1 & 0xFF) << (8 * i);
        }
        d0[lane + 32 * t] = p0;
        d1[lane + 32 * t] = p1;
    }
    if (lane == 0) sc[w] = s;
}

// ---------------------------------------------------------------------------
// GEMM1 (int8): gh[pair] = g * gelu(x[b] @ W1[e] + b1[e])  -> fp32
// BM=128, BN=128, kc=128 k-elems (128B); stage 64KB, 3 stages (192KB).
// 512 threads, warp tile 32x32 (MF2 NF4). Grid (16,2,64) = 2048 CTAs.
// ---------------------------------------------------------------------------
#define G1_STAGE 65536u
#define G1_SMEM  (3 * 65536)

__global__ void __launch_bounds__(512, 1)
gemm1_i8(const float* __restrict__ b1p) {
    extern __shared__ __align__(128) char smem[];
    const int tid = threadIdx.x, lane = tid & 31, wid = tid >> 5;
    const int pair = blockIdx.z, bb = pair >> 1;
    const int e = g_pair_e[pair];
    const float g = g_pair_g[pair];
    const int m0 = blockIdx.y * 128, n0 = blockIdx.x * 128;

    const uint8_t* Aq = (const uint8_t*)g_xq  + (size_t)(bb * L_ + m0) * 1024;
    const uint8_t* Bq = (const uint8_t*)g_w1q + ((size_t)e * FF_ + n0) * 1024;

    uint32_t s0 = smem_u32(smem);
    const int wm = (wid >> 2) * 32, wn = (wid & 3) * 32;

    int acc0[2][4][4] = {}, acc1[2][4][4] = {};
    const int NC = 4;   // 512 / 128

#define G1_LOAD(c, buf) do { int _k = (c) * 128; uint32_t _d = s0 + (buf) * G1_STAGE; \
        load_tile_b<128, 512>(_d,          Aq + _k,       1024, tid); \
        load_tile_b<128, 512>(_d + 16384u, Aq + 512 + _k, 1024, tid); \
        load_tile_b<128, 512>(_d + 32768u, Bq + _k,       1024, tid); \
        load_tile_b<128, 512>(_d + 49152u, Bq + 512 + _k, 1024, tid); \
        CP_COMMIT(); } while (0)

    G1_LOAD(0, 0);
    G1_LOAD(1, 1);
    for (int c = 0; c < NC; c++) {
        if (c == NC - 1) asm volatile("cp.async.wait_group 0;" ::: "memory");
        else             asm volatile("cp.async.wait_group 1;" ::: "memory");
        __syncthreads();
        if (c + 2 < NC) G1_LOAD(c + 2, (uint32_t)((c + 2) % 3));
        uint32_t sb = s0 + (uint32_t)(c % 3) * G1_STAGE;
        compute_i8<2, 4>(acc0, acc1, sb, sb + 16384u, sb + 32768u, sb + 49152u, wm, wn, lane);
    }
#undef G1_LOAD

    // epilogue: dequant, +bias, gelu, *gate, store fp32 gh
    const float* b1e = b1p + (size_t)e * FF_;
#pragma unroll
    for (int mf = 0; mf < 2; mf++) {
#pragma unroll
        for (int h = 0; h < 2; h++) {
            int r = wm + mf * 16 + (lane >> 2) + 8 * h;
            float sa = g_xs[bb * L_ + m0 + r];
            float* op = g_gh + ((size_t)pair * L_ + m0 + r) * FF_;
#pragma unroll
            for (int nf = 0; nf < 4; nf++) {
                int n = n0 + wn + nf * 8 + (lane & 3) * 2;
                float sb0 = __ldg(&g_w1s[e * FF_ + n]);
                float sb1 = __ldg(&g_w1s[e * FF_ + n + 1]);
                float v0 = sa * sb0 * ((float)acc0[mf][nf][2 * h + 0] + 0.0078125f * (float)acc1[mf][nf][2 * h + 0]) + __ldg(b1e + n);
                float v1 = sa * sb1 * ((float)acc0[mf][nf][2 * h + 1] + 0.0078125f * (float)acc1[mf][nf][2 * h + 1]) + __ldg(b1e + n + 1);
                float2 o;
                o.x = gelu_exact(v0) * g;
                o.y = gelu_exact(v1) * g;
                *(float2*)(op + n) = o;
            }
        }
    }
}

// ---------------------------------------------------------------------------
// GEMM2 (int8, slot-split): part[pair] = (g*h)[pair] @ W2[e_pair]
// BM=128, BN=64, kc=128; stage = 16+16+8+8 = 48KB, 2 stages (96KB) -> 2 CTAs/SM.
// 256 threads, warp tile 32x32. Grid (8,2,64) = 1024 CTAs. K=2048 (16 chunks).
// ---------------------------------------------------------------------------
#define H2_STAGE 49152u
#define H2_SMEM  (2 * 49152)

__global__ void __launch_bounds__(256, 2)
gemm2_i8() {
    extern __shared__ __align__(128) char smem[];
    const int tid = threadIdx.x, lane = tid & 31, wid = tid >> 5;
    const int pair = blockIdx.z;
    const int e = g_pair_e[pair];
    const int m0 = blockIdx.y * 128, n0 = blockIdx.x * 64;

    const uint8_t* Aq = (const uint8_t*)g_ghq + ((size_t)pair * L_ + m0) * 4096;
    const uint8_t* Bq = (const uint8_t*)g_w2q + ((size_t)e * DM_ + n0) * 4096;

    uint32_t s0 = smem_u32(smem);
    const int wm = (wid >> 1) * 32, wn = (wid & 1) * 32;

    int acc0[2][4][4] = {}, acc1[2][4][4] = {};
    const int NC = 16;   // 2048 / 128

#define G2_LOAD(c, buf) do { int _k = (c) * 128; uint32_t _d = s0 + (buf) * H2_STAGE; \
        load_tile_b<128, 256>(_d,          Aq + _k,        4096, tid); \
        load_tile_b<128, 256>(_d + 16384u, Aq + 2048 + _k, 4096, tid); \
        load_tile_b<64, 256> (_d + 32768u, Bq + _k,        4096, tid); \
        load_tile_b<64, 256> (_d + 40960u, Bq + 2048 + _k, 4096, tid); \
        CP_COMMIT(); } while (0)

    G2_LOAD(0, 0);
    G2_LOAD(1, 1);
    for (int c = 0; c < NC; c++) {
        if (c == NC - 1) asm volatile("cp.async.wait_group 0;" ::: "memory");
        else             asm volatile("cp.async.wait_group 1;" ::: "memory");
        __syncthreads();
        uint32_t sb = s0 + (uint32_t)(c & 1) * H2_STAGE;
        compute_i8<2, 4>(acc0, acc1, sb, sb + 16384u, sb + 32768u, sb + 40960u, wm, wn, lane);
        __syncthreads();
        if (c + 2 < NC) G2_LOAD(c + 2, (c + 2) & 1);
    }
#undef G2_LOAD

    // epilogue: dequant -> fp32 partial
#pragma unroll
    for (int mf = 0; mf < 2; mf++) {
#pragma unroll
        for (int h = 0; h < 2; h++) {
            int r = wm + mf * 16 + (lane >> 2) + 8 * h;
            float sa = g_ghs[pair * L_ + m0 + r];
            float* op = g_part + ((size_t)pair * L_ + m0 + r) * DM_;
#pragma unroll
            for (int nf = 0; nf < 4; nf++) {
                int n = n0 + wn + nf * 8 + (lane & 3) * 2;
                float sb0 = __ldg(&g_w2s[e * DM_ + n]);
                float sb1 = __ldg(&g_w2s[e * DM_ + n + 1]);
                float2 o;
                o.x = sa * sb0 * ((float)acc0[mf][nf][2 * h + 0] + 0.0078125f * (float)acc1[mf][nf][2 * h + 0]);
                o.y = sa * sb1 * ((float)acc0[mf][nf][2 * h + 1] + 0.0078125f * (float)acc1[mf][nf][2 * h + 1]);
                *(float2*)(op + n) = o;
            }
        }
    }
}

// ---------------------------------------------------------------------------
// combine: out[b,l,:] = part[2b] + part[2b+1] + g0*b2[e0] + g1*b2[e1]
// ---------------------------------------------------------------------------
__global__ void combine_kernel(const float* __restrict__ b2p, float* __restrict__ out) {
    size_t i = (size_t)blockIdx.x * blockDim.x + threadIdx.x;
    size_t row = i / (DM_ / 4);
    int n4 = (int)(i % (DM_ / 4));
    int b = (int)(row / L_);
    int e0 = g_pair_e[2 * b + 0], e1 = g_pair_e[2 * b + 1];
    float g0 = g_pair_g[2 * b + 0], g1 = g_pair_g[2 * b + 1];

    const float4* p0 = (const float4*)(g_part + ((size_t)(2 * b + 0) * L_ + (row % L_)) * DM_);
    const float4* p1 = (const float4*)(g_part + ((size_t)(2 * b + 1) * L_ + (row % L_)) * DM_);
    const float4* bb0 = (const float4*)(b2p + (size_t)e0 * DM_);
    const float4* bb1 = (const float4*)(b2p + (size_t)e1 * DM_);

    float4 a = p0[n4], c = p1[n4], d0 = __ldg(bb0 + n4), d1 = __ldg(bb1 + n4);
    float4 r;
    r.x = a.x + c.x + g0 * d0.x + g1 * d1.x;
    r.y = a.y + c.y + g0 * d0.y + g1 * d1.y;
    r.z = a.z + c.z + g0 * d0.z + g1 * d1.z;
    r.w = a.w + c.w + g0 * d0.w + g1 * d1.w;
    ((float4*)out)[i] = r;
}

// ---------------------------------------------------------------------------
// launch — kernel launches + idempotent attribute opt-ins (no statics)
// ---------------------------------------------------------------------------
extern "C" void kernel_launch(void* const* d_in, const int* in_sizes, int n_in,
                              void* d_out, int out_size) {
    const float* x      = (const float*)d_in[0];
    const float* logits = (const float*)d_in[1];
    const int*   masks  = (const int*)  d_in[2];
    const float* W1     = (const float*)d_in[3];
    const float* b1     = (const float*)d_in[4];
    const float* W2     = (const float*)d_in[5];
    const float* b2     = (const float*)d_in[6];
    float* out = (float*)d_out;

    cudaFuncSetAttribute(gemm1_i8, cudaFuncAttributeMaxDynamicSharedMemorySize, G1_SMEM);
    cudaFuncSetAttribute(gemm2_i8, cudaFuncAttributeMaxDynamicSharedMemorySize, H2_SMEM);

    prep_kernel<<<16385, 256>>>(logits, masks, W1, W2);
    rq_kernel<<<1024, 256>>>(0, x);        // x rows
    rq_kernel<<<2048, 256>>>(1, x);        // W1^T rows
    rq_kernel<<<512, 256>>>(2, x);         // W2^T rows

    gemm1_i8<<<dim3(FF_ / 128, L_ / 128, NPAIR), 512, G1_SMEM>>>(b1);
    rq_kernel<<<2048, 256>>>(3, x);        // gh rows

    gemm2_i8<<<dim3(DM_ / 64, L_ / 128, NPAIR), 256, H2_SMEM>>>();

    size_t nq = (size_t)B_ * L_ * DM_ / 4;
    combine_kernel<<<(unsigned)((nq + 255) / 256), 256>>>(b2, out);
}

// round 11
// speedup vs baseline: 2.5924x; 2.5924x over previous
#include <cuda_runtime.h>
#include <cuda_bf16.h>
#include <math.h>
#include <stdint.h>

#define B_   32
#define L_   256
#define DM_  512
#define FF_  2048
#define E_   8
#define NPAIR 64

// ---------------- device scratch (static = allocation-free) ----------------
__device__ int   g_pair_e[NPAIR];
__device__ float g_pair_g[NPAIR];
// x split:  [B*L][2*DM]   row = [hi(0..511) | lo(0..511)]
__device__ __align__(256) __nv_bfloat16 g_x2[(size_t)B_ * L_ * 2 * DM_];
// W1^T split: [E][FF][2*DM]
__device__ __align__(256) __nv_bfloat16 g_w1t[(size_t)E_ * FF_ * 2 * DM_];
// W2^T split: [E][DM][2*FF]
__device__ __align__(256) __nv_bfloat16 g_w2t[(size_t)E_ * DM_ * 2 * FF_];
// g*gelu(h) split: [pair][L][2*FF]
__device__ __align__(256) __nv_bfloat16 g_gh[(size_t)NPAIR * L_ * 2 * FF_];
// per-pair fp32 partials of GEMM2 (slot-split)
__device__ __align__(256) float g_part[(size_t)NPAIR * L_ * DM_];

// ---------------- helpers ----------------
__device__ __forceinline__ uint32_t smem_u32(const void* p) {
    uint32_t a;
    asm("{ .reg .u64 t; cvta.to.shared.u64 t, %1; cvt.u32.u64 %0, t; }" : "=r"(a) : "l"(p));
    return a;
}
__device__ __forceinline__ void cp16(uint32_t dst, const void* src) {
    asm volatile("cp.async.cg.shared.global [%0], [%1], 16;" :: "r"(dst), "l"(src));
}
#define CP_COMMIT() asm volatile("cp.async.commit_group;" ::: "memory")

__device__ __forceinline__ void ldsm_x4(uint32_t& r0, uint32_t& r1, uint32_t& r2, uint32_t& r3, uint32_t a) {
    asm volatile("ldmatrix.sync.aligned.m8n8.x4.shared.b16 {%0,%1,%2,%3}, [%4];"
                 : "=r"(r0), "=r"(r1), "=r"(r2), "=r"(r3) : "r"(a));
}
__device__ __forceinline__ void mma_bf16(float* c, const uint32_t* a, uint32_t b0, uint32_t b1) {
    asm volatile("mma.sync.aligned.m16n8k16.row.col.f32.bf16.bf16.f32 "
                 "{%0,%1,%2,%3}, {%4,%5,%6,%7}, {%8,%9}, {%0,%1,%2,%3};"
                 : "+f"(c[0]), "+f"(c[1]), "+f"(c[2]), "+f"(c[3])
                 : "r"(a[0]), "r"(a[1]), "r"(a[2]), "r"(a[3]), "r"(b0), "r"(b1));
}
__device__ __forceinline__ float gelu_exact(float x) {
    return 0.5f * x * (1.0f + erff(x * 0.70710678118654752440f));
}

// Load a ROWS x 64 bf16 tile (128B rows, XOR swizzle chunk^=(row&7)) via cp.async.
template<int ROWS, int NT>
__device__ __forceinline__ void load_tile(uint32_t dst, const __nv_bfloat16* src, int ld, int tid) {
    constexpr int ITER = ROWS * 8 / NT;
#pragma unroll
    for (int j = 0; j < ITER; j++) {
        int idx = tid + j * NT;
        int r = idx >> 3, c = idx & 7;
        uint32_t off = (uint32_t)(r * 128 + ((c ^ (r & 7)) * 16));
        cp16(dst + off, (const char*)src + (size_t)r * ld * 2 + c * 16);
    }
}

// Fused 3-term chunk: load Ah/Al/Bh/Bl fragments once, issue AhBh+AlBh+AhBl.
template<int MF, int NF>
__device__ __forceinline__ void compute_fused(float (&acc)[MF][NF][4],
                                              uint32_t aH, uint32_t aL,
                                              uint32_t bH, uint32_t bL,
                                              int wm, int wn, int lane) {
#pragma unroll
    for (int ks = 0; ks < 4; ks++) {
        uint32_t ah[MF][4], al[MF][4];
#pragma unroll
        for (int mf = 0; mf < MF; mf++) {
            int r = wm + mf * 16 + (lane & 15);
            int c = ks * 2 + (lane >> 4);
            uint32_t off = (uint32_t)(r * 128 + ((c ^ (r & 7)) * 16));
            ldsm_x4(ah[mf][0], ah[mf][1], ah[mf][2], ah[mf][3], aH + off);
            ldsm_x4(al[mf][0], al[mf][1], al[mf][2], al[mf][3], aL + off);
        }
#pragma unroll
        for (int nfp = 0; nfp < NF / 2; nfp++) {
            int q = lane >> 3;
            int r = wn + (nfp * 2 + (q >> 1)) * 8 + (lane & 7);
            int c = ks * 2 + (q & 1);
            uint32_t off = (uint32_t)(r * 128 + ((c ^ (r & 7)) * 16));
            uint32_t bh0, bh1, bh2, bh3, bl0, bl1, bl2, bl3;
            ldsm_x4(bh0, bh1, bh2, bh3, bH + off);
            ldsm_x4(bl0, bl1, bl2, bl3, bL + off);
#pragma unroll
            for (int mf = 0; mf < MF; mf++) {
                mma_bf16(acc[mf][2 * nfp],     ah[mf], bh0, bh1);
                mma_bf16(acc[mf][2 * nfp + 1], ah[mf], bh2, bh3);
                mma_bf16(acc[mf][2 * nfp],     al[mf], bh0, bh1);
                mma_bf16(acc[mf][2 * nfp + 1], al[mf], bh2, bh3);
                mma_bf16(acc[mf][2 * nfp],     ah[mf], bl0, bl1);
                mma_bf16(acc[mf][2 * nfp + 1], ah[mf], bl2, bl3);
            }
        }
    }
}

// ---------------------------------------------------------------------------
// Fused prep: gates + x hi/lo split + W1^T split + W2^T split in ONE launch.
// ---------------------------------------------------------------------------
__device__ __forceinline__ void transpose_sec(const float* __restrict__ W,
                                              __nv_bfloat16* __restrict__ T,
                                              int K, int N, int bx, int by, int bz,
                                              int tx, int ty, float (*s)[33]) {
    int n0 = bx * 32, k0 = by * 32;
    const float* Wp = W + (size_t)bz * K * N;
#pragma unroll
    for (int i = 0; i < 32; i += 8)
        s[ty + i][tx] = Wp[(size_t)(k0 + ty + i) * N + n0 + tx];
    __syncthreads();
#pragma unroll
    for (int i = 0; i < 32; i += 8) {
        int n = n0 + ty + i;
        int k = k0 + tx;
        float v = s[tx][ty + i];
        __nv_bfloat16 h = __float2bfloat16(v);
        __nv_bfloat16* rowp = T + ((size_t)bz * N + n) * (2 * (size_t)K);
        rowp[k]     = h;
        rowp[K + k] = __float2bfloat16(v - __bfloat162float(h));
    }
}

__global__ void prep_kernel(const float* __restrict__ X,
                            const float* __restrict__ logits,
                            const int*   __restrict__ masks,
                            const float* __restrict__ W1,
                            const float* __restrict__ W2) {
    __shared__ float s[32][33];
    const int blk = blockIdx.x;
    const int tid = threadIdx.x;
    const int tx = tid & 31, ty = tid >> 5;

    if (blk < 16384) {
        // x split
        size_t i = (size_t)blk * 256 + tid;
        size_t row = i / DM_;
        int k = (int)(i % DM_);
        float v = X[i];
        __nv_bfloat16 h = __float2bfloat16(v);
        g_x2[row * (2 * DM_) + k] = h;
        g_x2[row * (2 * DM_) + DM_ + k] = __float2bfloat16(v - __bfloat162float(h));
    } else if (blk < 24576) {
        int i = blk - 16384;                       // W1: bx<64, by<16, bz<8
        transpose_sec(W1, g_w1t, DM_, FF_, i & 63, (i >> 6) & 15, i >> 10, tx, ty, s);
    } else if (blk < 32768) {
        int i = blk - 24576;                       // W2: bx<16, by<64, bz<8
        transpose_sec(W2, g_w2t, FF_, DM_, i & 15, (i >> 4) & 63, i >> 10, tx, ty, s);
    } else {
        // gates
        int b = tid;
        if (b >= B_) return;
        float p[E_];
        float mx = -1e30f;
#pragma unroll
        for (int i = 0; i < E_; i++) { p[i] = logits[b * E_ + i]; mx = fmaxf(mx, p[i]); }
        float sum = 0.0f;
#pragma unroll
        for (int i = 0; i < E_; i++) { p[i] = expf(p[i] - mx); sum += p[i]; }
        float inv = 1.0f / sum;
#pragma unroll
        for (int i = 0; i < E_; i++) p[i] = (masks[b * E_ + i] == 1) ? p[i] * inv : 0.0f;
        int i1 = 0;
#pragma unroll
        for (int i = 1; i < E_; i++) if (p[i] > p[i1]) i1 = i;
        int i2 = -1;
#pragma unroll
        for (int i = 0; i < E_; i++) {
            if (i == i1) continue;
            if (i2 < 0 || p[i] > p[i2]) i2 = i;
        }
        float denom = p[i1] + p[i2] + 1e-9f;
        g_pair_e[2 * b + 0] = i1;  g_pair_g[2 * b + 0] = p[i1] / denom;
        g_pair_e[2 * b + 1] = i2;  g_pair_g[2 * b + 1] = p[i2] / denom;
    }
}

// ---------------------------------------------------------------------------
// GEMM1 (R7/R9 config, measured best): gh[pair] = g * gelu(x[b] @ W1[e] + b1[e])
// BM=128, BN=256, kc=64; stage 96KB; 2 stages (192KB); 512 threads;
// warp tile 32x64 (MF=2, NF=8). Grid (8,2,64) = 1024 CTAs.
// ---------------------------------------------------------------------------
#define G1_STAGE  98304u
#define G1_A_L    16384u
#define G1_B_H    32768u
#define G1_B_L    65536u
#define G1_SMEM   (2 * 98304)

__global__ void __launch_bounds__(512, 1)
gemm1_mma(const float* __restrict__ b1p) {
    extern __shared__ __align__(128) char smem[];
    const int tid = threadIdx.x, lane = tid & 31, wid = tid >> 5;
    const int pair = blockIdx.z;
    const int e = g_pair_e[pair];
    const float g = g_pair_g[pair];
    const int m0 = blockIdx.y * 128, n0 = blockIdx.x * 256;

    const __nv_bfloat16* Abase = g_x2  + ((size_t)(pair >> 1) * L_ + m0) * (2 * DM_);
    const __nv_bfloat16* Bbase = g_w1t + ((size_t)e * FF_ + n0) * (2 * DM_);

    uint32_t s0 = smem_u32(smem);
    const int wm = (wid >> 2) * 32, wn = (wid & 3) * 64;   // warp tile 32x64

    float acc[2][8][4] = {};
    const int NC = 8;   // 512 / 64

#define G1_LOAD(c, buf) do { int _k = (c) * 64; uint32_t _d = s0 + (buf) * G1_STAGE; \
        load_tile<128, 512>(_d,          Abase + _k,       2 * DM_, tid); \
        load_tile<128, 512>(_d + G1_A_L, Abase + DM_ + _k, 2 * DM_, tid); \
        load_tile<256, 512>(_d + G1_B_H, Bbase + _k,       2 * DM_, tid); \
        load_tile<256, 512>(_d + G1_B_L, Bbase + DM_ + _k, 2 * DM_, tid); \
        CP_COMMIT(); } while (0)

    G1_LOAD(0, 0);
    G1_LOAD(1, 1);
    for (int c = 0; c < NC; c++) {
        if (c == NC - 1) asm volatile("cp.async.wait_group 0;" ::: "memory");
        else             asm volatile("cp.async.wait_group 1;" ::: "memory");
        __syncthreads();
        uint32_t sb = s0 + (uint32_t)(c & 1) * G1_STAGE;
        compute_fused<2, 8>(acc, sb, sb + G1_A_L, sb + G1_B_H, sb + G1_B_L, wm, wn, lane);
        __syncthreads();
        if (c + 2 < NC) G1_LOAD(c + 2, (c + 2) & 1);
    }
#undef G1_LOAD

    // epilogue: +bias, gelu, *gate, split hi/lo, store
    const float* b1e = b1p + (size_t)e * FF_;
#pragma unroll
    for (int mf = 0; mf < 2; mf++) {
#pragma unroll
        for (int h = 0; h < 2; h++) {
            int r = m0 + wm + mf * 16 + (lane >> 2) + 8 * h;
            __nv_bfloat16* rowp = g_gh + ((size_t)pair * L_ + r) * (2 * FF_);
#pragma unroll
            for (int nf = 0; nf < 8; nf++) {
                int n = n0 + wn + nf * 8 + (lane & 3) * 2;
                float v0 = acc[mf][nf][2 * h + 0] + __ldg(b1e + n);
                float v1 = acc[mf][nf][2 * h + 1] + __ldg(b1e + n + 1);
                v0 = gelu_exact(v0) * g;
                v1 = gelu_exact(v1) * g;
                __nv_bfloat16 h0 = __float2bfloat16(v0), h1 = __float2bfloat16(v1);
                __nv_bfloat162 hv; hv.x = h0; hv.y = h1;
                __nv_bfloat162 lv;
                lv.x = __float2bfloat16(v0 - __bfloat162float(h0));
                lv.y = __float2bfloat16(v1 - __bfloat162float(h1));
                *(__nv_bfloat162*)(rowp + n)       = hv;
                *(__nv_bfloat162*)(rowp + FF_ + n) = lv;
            }
        }
    }
}

// ---------------------------------------------------------------------------
// GEMM2 (slot-split, BN=128): part[pair] = (g*h)[pair] @ W2[e_pair]
// BM=128, BN=128, kc=64; stage 64KB; 3 stages (192KB), 1 sync/iter.
// 512 threads, warp tile 32x32. Grid (4,2,64) = 512 CTAs. K = 2048 (32 chunks).
// A-traffic halved vs BN=64 (gh read 4x instead of 8x).
// ---------------------------------------------------------------------------
#define G2_STAGE  65536u
#define G2_A_L    16384u
#define G2_B_H    32768u
#define G2_B_L    49152u
#define G2_SMEM   (3 * 65536)

__global__ void __launch_bounds__(512, 1)
gemm2_mma() {
    extern __shared__ __align__(128) char smem[];
    const int tid = threadIdx.x, lane = tid & 31, wid = tid >> 5;
    const int pair = blockIdx.z;
    const int e = g_pair_e[pair];
    const int m0 = blockIdx.y * 128, n0 = blockIdx.x * 128;

    const __nv_bfloat16* Abase = g_gh  + ((size_t)pair * L_ + m0) * (2 * FF_);
    const __nv_bfloat16* Bbase = g_w2t + ((size_t)e * DM_ + n0) * (2 * FF_);

    uint32_t s0 = smem_u32(smem);
    const int wm = (wid >> 2) * 32, wn = (wid & 3) * 32;   // warp tile 32x32

    float acc[2][4][4] = {};
    const int NC = 32;   // 2048 / 64

#define G2_LOAD(c, buf) do { int _k = (c) * 64; uint32_t _d = s0 + (buf) * G2_STAGE; \
        load_tile<128, 512>(_d,          Abase + _k,       2 * FF_, tid); \
        load_tile<128, 512>(_d + G2_A_L, Abase + FF_ + _k, 2 * FF_, tid); \
        load_tile<128, 512>(_d + G2_B_H, Bbase + _k,       2 * FF_, tid); \
        load_tile<128, 512>(_d + G2_B_L, Bbase + FF_ + _k, 2 * FF_, tid); \
        CP_COMMIT(); } while (0)

    G2_LOAD(0, 0);
    G2_LOAD(1, 1);
    for (int c = 0; c < NC; c++) {
        if (c == NC - 1) asm volatile("cp.async.wait_group 0;" ::: "memory");
        else             asm volatile("cp.async.wait_group 1;" ::: "memory");
        __syncthreads();
        if (c + 2 < NC) G2_LOAD(c + 2, (uint32_t)((c + 2) % 3));
        uint32_t sb = s0 + (uint32_t)(c % 3) * G2_STAGE;
        compute_fused<2, 4>(acc, sb, sb + G2_A_L, sb + G2_B_H, sb + G2_B_L, wm, wn, lane);
    }
#undef G2_LOAD

    // store fp32 partials (bias added in combine)
#pragma unroll
    for (int mf = 0; mf < 2; mf++) {
#pragma unroll
        for (int h = 0; h < 2; h++) {
            int r = wm + mf * 16 + (lane >> 2) + 8 * h;
            float* op = g_part + ((size_t)pair * L_ + m0 + r) * DM_;
#pragma unroll
            for (int nf = 0; nf < 4; nf++) {
                int n = n0 + wn + nf * 8 + (lane & 3) * 2;
                float2 v;
                v.x = acc[mf][nf][2 * h + 0];
                v.y = acc[mf][nf][2 * h + 1];
                *(float2*)(op + n) = v;
            }
        }
    }
}

// ---------------------------------------------------------------------------
// combine: out[b,l,:] = part[2b] + part[2b+1] + g0*b2[e0] + g1*b2[e1]
// ---------------------------------------------------------------------------
__global__ void combine_kernel(const float* __restrict__ b2p, float* __restrict__ out) {
    size_t i = (size_t)blockIdx.x * blockDim.x + threadIdx.x;
    size_t row = i / (DM_ / 4);
    int n4 = (int)(i % (DM_ / 4));
    int b = (int)(row / L_);
    int e0 = g_pair_e[2 * b + 0], e1 = g_pair_e[2 * b + 1];
    float g0 = g_pair_g[2 * b + 0], g1 = g_pair_g[2 * b + 1];

    const float4* p0 = (const float4*)(g_part + ((size_t)(2 * b + 0) * L_ + (row % L_)) * DM_);
    const float4* p1 = (const float4*)(g_part + ((size_t)(2 * b + 1) * L_ + (row % L_)) * DM_);
    const float4* bb0 = (const float4*)(b2p + (size_t)e0 * DM_);
    const float4* bb1 = (const float4*)(b2p + (size_t)e1 * DM_);

    float4 a = p0[n4], c = p1[n4], d0 = __ldg(bb0 + n4), d1 = __ldg(bb1 + n4);
    float4 r;
    r.x = a.x + c.x + g0 * d0.x + g1 * d1.x;
    r.y = a.y + c.y + g0 * d0.y + g1 * d1.y;
    r.z = a.z + c.z + g0 * d0.z + g1 * d1.z;
    r.w = a.w + c.w + g0 * d0.w + g1 * d1.w;
    ((float4*)out)[i] = r;
}

// ---------------------------------------------------------------------------
// launch — kernel launches + idempotent attribute opt-ins (no statics)
// ---------------------------------------------------------------------------
extern "C" void kernel_launch(void* const* d_in, const int* in_sizes, int n_in,
                              void* d_out, int out_size) {
    const float* x      = (const float*)d_in[0];
    const float* logits = (const float*)d_in[1];
    const int*   masks  = (const int*)  d_in[2];
    const float* W1     = (const float*)d_in[3];
    const float* b1     = (const float*)d_in[4];
    const float* W2     = (const float*)d_in[5];
    const float* b2     = (const float*)d_in[6];
    float* out = (float*)d_out;

    cudaFuncSetAttribute(gemm1_mma, cudaFuncAttributeMaxDynamicSharedMemorySize, G1_SMEM);
    cudaFuncSetAttribute(gemm2_mma, cudaFuncAttributeMaxDynamicSharedMemorySize, G2_SMEM);

    prep_kernel<<<32769, 256>>>(x, logits, masks, W1, W2);

    gemm1_mma<<<dim3(FF_ / 256, L_ / 128, NPAIR), 512, G1_SMEM>>>(b1);
    gemm2_mma<<<dim3(DM_ / 128, L_ / 128, NPAIR), 512, G2_SMEM>>>();

    size_t nq = (size_t)B_ * L_ * DM_ / 4;
    combine_kernel<<<(unsigned)((nq + 255) / 256), 256>>>(b2, out);
}

// round 12
// speedup vs baseline: 2.7803x; 1.0725x over previous
#include <cuda_runtime.h>
#include <cuda_bf16.h>
#include <math.h>
#include <stdint.h>

#define B_   32
#define L_   256
#define DM_  512
#define FF_  2048
#define E_   8
#define NPAIR 64

// ---------------- device scratch (static = allocation-free) ----------------
__device__ int   g_pair_e[NPAIR];
__device__ float g_pair_g[NPAIR];
// x split:  [B*L][2*DM]   row = [hi(0..511) | lo(0..511)]
__device__ __align__(256) __nv_bfloat16 g_x2[(size_t)B_ * L_ * 2 * DM_];
// W1^T split: [E][FF][2*DM]
__device__ __align__(256) __nv_bfloat16 g_w1t[(size_t)E_ * FF_ * 2 * DM_];
// W2^T split: [E][DM][2*FF]
__device__ __align__(256) __nv_bfloat16 g_w2t[(size_t)E_ * DM_ * 2 * FF_];
// g*gelu(h) split: [pair][L][2*FF]
__device__ __align__(256) __nv_bfloat16 g_gh[(size_t)NPAIR * L_ * 2 * FF_];

// ---------------- helpers ----------------
__device__ __forceinline__ uint32_t smem_u32(const void* p) {
    uint32_t a;
    asm("{ .reg .u64 t; cvta.to.shared.u64 t, %1; cvt.u32.u64 %0, t; }" : "=r"(a) : "l"(p));
    return a;
}
__device__ __forceinline__ void cp16(uint32_t dst, const void* src) {
    asm volatile("cp.async.cg.shared.global [%0], [%1], 16;" :: "r"(dst), "l"(src));
}
#define CP_COMMIT() asm volatile("cp.async.commit_group;" ::: "memory")

__device__ __forceinline__ void ldsm_x4(uint32_t& r0, uint32_t& r1, uint32_t& r2, uint32_t& r3, uint32_t a) {
    asm volatile("ldmatrix.sync.aligned.m8n8.x4.shared.b16 {%0,%1,%2,%3}, [%4];"
                 : "=r"(r0), "=r"(r1), "=r"(r2), "=r"(r3) : "r"(a));
}
__device__ __forceinline__ void mma_bf16(float* c, const uint32_t* a, uint32_t b0, uint32_t b1) {
    asm volatile("mma.sync.aligned.m16n8k16.row.col.f32.bf16.bf16.f32 "
                 "{%0,%1,%2,%3}, {%4,%5,%6,%7}, {%8,%9}, {%0,%1,%2,%3};"
                 : "+f"(c[0]), "+f"(c[1]), "+f"(c[2]), "+f"(c[3])
                 : "r"(a[0]), "r"(a[1]), "r"(a[2]), "r"(a[3]), "r"(b0), "r"(b1));
}
__device__ __forceinline__ float gelu_exact(float x) {
    return 0.5f * x * (1.0f + erff(x * 0.70710678118654752440f));
}

// Load a ROWS x 64 bf16 tile (128B rows, XOR swizzle chunk^=(row&7)) via cp.async.
template<int ROWS, int NT>
__device__ __forceinline__ void load_tile(uint32_t dst, const __nv_bfloat16* src, int ld, int tid) {
    constexpr int ITER = ROWS * 8 / NT;
#pragma unroll
    for (int j = 0; j < ITER; j++) {
        int idx = tid + j * NT;
        int r = idx >> 3, c = idx & 7;
        uint32_t off = (uint32_t)(r * 128 + ((c ^ (r & 7)) * 16));
        cp16(dst + off, (const char*)src + (size_t)r * ld * 2 + c * 16);
    }
}

// Fused 3-term chunk: load Ah/Al/Bh/Bl fragments once, issue AhBh+AlBh+AhBl.
template<int MF, int NF>
__device__ __forceinline__ void compute_fused(float (&acc)[MF][NF][4],
                                              uint32_t aH, uint32_t aL,
                                              uint32_t bH, uint32_t bL,
                                              int wm, int wn, int lane) {
#pragma unroll
    for (int ks = 0; ks < 4; ks++) {
        uint32_t ah[MF][4], al[MF][4];
#pragma unroll
        for (int mf = 0; mf < MF; mf++) {
            int r = wm + mf * 16 + (lane & 15);
            int c = ks * 2 + (lane >> 4);
            uint32_t off = (uint32_t)(r * 128 + ((c ^ (r & 7)) * 16));
            ldsm_x4(ah[mf][0], ah[mf][1], ah[mf][2], ah[mf][3], aH + off);
            ldsm_x4(al[mf][0], al[mf][1], al[mf][2], al[mf][3], aL + off);
        }
#pragma unroll
        for (int nfp = 0; nfp < NF / 2; nfp++) {
            int q = lane >> 3;
            int r = wn + (nfp * 2 + (q >> 1)) * 8 + (lane & 7);
            int c = ks * 2 + (q & 1);
            uint32_t off = (uint32_t)(r * 128 + ((c ^ (r & 7)) * 16));
            uint32_t bh0, bh1, bh2, bh3, bl0, bl1, bl2, bl3;
            ldsm_x4(bh0, bh1, bh2, bh3, bH + off);
            ldsm_x4(bl0, bl1, bl2, bl3, bL + off);
#pragma unroll
            for (int mf = 0; mf < MF; mf++) {
                mma_bf16(acc[mf][2 * nfp],     ah[mf], bh0, bh1);
                mma_bf16(acc[mf][2 * nfp + 1], ah[mf], bh2, bh3);
                mma_bf16(acc[mf][2 * nfp],     al[mf], bh0, bh1);
                mma_bf16(acc[mf][2 * nfp + 1], al[mf], bh2, bh3);
                mma_bf16(acc[mf][2 * nfp],     ah[mf], bl0, bl1);
                mma_bf16(acc[mf][2 * nfp + 1], ah[mf], bl2, bl3);
            }
        }
    }
}

// ---------------------------------------------------------------------------
// Fused prep: gates + x hi/lo split (float4) + W1^T split + W2^T split.
//   [0, 4096)       : x split (1024 elems per block, float4)
//   [4096, 12288)   : W1 transpose tiles (64 x 16 x 8)
//   [12288, 20480)  : W2 transpose tiles (16 x 64 x 8)
//   [20480]         : gates (first 32 threads)
// ---------------------------------------------------------------------------
__device__ __forceinline__ void transpose_sec(const float* __restrict__ W,
                                              __nv_bfloat16* __restrict__ T,
                                              int K, int N, int bx, int by, int bz,
                                              int tx, int ty, float (*s)[33]) {
    int n0 = bx * 32, k0 = by * 32;
    const float* Wp = W + (size_t)bz * K * N;
#pragma unroll
    for (int i = 0; i < 32; i += 8)
        s[ty + i][tx] = Wp[(size_t)(k0 + ty + i) * N + n0 + tx];
    __syncthreads();
#pragma unroll
    for (int i = 0; i < 32; i += 8) {
        int n = n0 + ty + i;
        int k = k0 + tx;
        float v = s[tx][ty + i];
        __nv_bfloat16 h = __float2bfloat16(v);
        __nv_bfloat16* rowp = T + ((size_t)bz * N + n) * (2 * (size_t)K);
        rowp[k]     = h;
        rowp[K + k] = __float2bfloat16(v - __bfloat162float(h));
    }
}

__global__ void prep_kernel(const float* __restrict__ X,
                            const float* __restrict__ logits,
                            const int*   __restrict__ masks,
                            const float* __restrict__ W1,
                            const float* __restrict__ W2) {
    __shared__ float s[32][33];
    const int blk = blockIdx.x;
    const int tid = threadIdx.x;
    const int tx = tid & 31, ty = tid >> 5;

    if (blk < 4096) {
        // x split, 4 elems/thread via float4 (all 4 in same row: DM_%4==0)
        size_t i4 = (size_t)blk * 256 + tid;       // float4 index
        size_t row = i4 / (DM_ / 4);
        int k4 = (int)(i4 % (DM_ / 4));
        float4 v = ((const float4*)X)[i4];
        float vv[4] = {v.x, v.y, v.z, v.w};
        __nv_bfloat16 hh[4], ll[4];
#pragma unroll
        for (int t = 0; t < 4; t++) {
            hh[t] = __float2bfloat16(vv[t]);
            ll[t] = __float2bfloat16(vv[t] - __bfloat162float(hh[t]));
        }
        *(uint2*)(g_x2 + row * (2 * DM_) + k4 * 4)       = *(uint2*)hh;
        *(uint2*)(g_x2 + row * (2 * DM_) + DM_ + k4 * 4) = *(uint2*)ll;
    } else if (blk < 12288) {
        int i = blk - 4096;                        // W1: bx<64, by<16, bz<8
        transpose_sec(W1, g_w1t, DM_, FF_, i & 63, (i >> 6) & 15, i >> 10, tx, ty, s);
    } else if (blk < 20480) {
        int i = blk - 12288;                       // W2: bx<16, by<64, bz<8
        transpose_sec(W2, g_w2t, FF_, DM_, i & 15, (i >> 4) & 63, i >> 10, tx, ty, s);
    } else {
        // gates
        int b = tid;
        if (b >= B_) return;
        float p[E_];
        float mx = -1e30f;
#pragma unroll
        for (int i = 0; i < E_; i++) { p[i] = logits[b * E_ + i]; mx = fmaxf(mx, p[i]); }
        float sum = 0.0f;
#pragma unroll
        for (int i = 0; i < E_; i++) { p[i] = expf(p[i] - mx); sum += p[i]; }
        float inv = 1.0f / sum;
#pragma unroll
        for (int i = 0; i < E_; i++) p[i] = (masks[b * E_ + i] == 1) ? p[i] * inv : 0.0f;
        int i1 = 0;
#pragma unroll
        for (int i = 1; i < E_; i++) if (p[i] > p[i1]) i1 = i;
        int i2 = -1;
#pragma unroll
        for (int i = 0; i < E_; i++) {
            if (i == i1) continue;
            if (i2 < 0 || p[i] > p[i2]) i2 = i;
        }
        float denom = p[i1] + p[i2] + 1e-9f;
        g_pair_e[2 * b + 0] = i1;  g_pair_g[2 * b + 0] = p[i1] / denom;
        g_pair_e[2 * b + 1] = i2;  g_pair_g[2 * b + 1] = p[i2] / denom;
    }
}

// ---------------------------------------------------------------------------
// GEMM1: gh[pair] = g * gelu(x[b] @ W1[e] + b1[e])
// BM=128, BN=256, kc=64; stage 96KB; 2 stages (192KB).
// *** 256 threads, 8 warps 2x4, warp tile 64x64 (MF=4, NF=8) ***
// Tests MMA-issue-density theory: 6 MMA/ldsm vs 4 at 32x64.
// Grid (8,2,64) = 1024 CTAs.
// ---------------------------------------------------------------------------
#define G1_STAGE  98304u
#define G1_A_L    16384u
#define G1_B_H    32768u
#define G1_B_L    65536u
#define G1_SMEM   (2 * 98304)

__global__ void __launch_bounds__(256, 1)
gemm1_mma(const float* __restrict__ b1p) {
    extern __shared__ __align__(128) char smem[];
    const int tid = threadIdx.x, lane = tid & 31, wid = tid >> 5;
    const int pair = blockIdx.z;
    const int e = g_pair_e[pair];
    const float g = g_pair_g[pair];
    const int m0 = blockIdx.y * 128, n0 = blockIdx.x * 256;

    const __nv_bfloat16* Abase = g_x2  + ((size_t)(pair >> 1) * L_ + m0) * (2 * DM_);
    const __nv_bfloat16* Bbase = g_w1t + ((size_t)e * FF_ + n0) * (2 * DM_);

    uint32_t s0 = smem_u32(smem);
    const int wm = (wid >> 2) * 64, wn = (wid & 3) * 64;   // warp tile 64x64

    float acc[4][8][4] = {};
    const int NC = 8;   // 512 / 64

#define G1_LOAD(c, buf) do { int _k = (c) * 64; uint32_t _d = s0 + (buf) * G1_STAGE; \
        load_tile<128, 256>(_d,          Abase + _k,       2 * DM_, tid); \
        load_tile<128, 256>(_d + G1_A_L, Abase + DM_ + _k, 2 * DM_, tid); \
        load_tile<256, 256>(_d + G1_B_H, Bbase + _k,       2 * DM_, tid); \
        load_tile<256, 256>(_d + G1_B_L, Bbase + DM_ + _k, 2 * DM_, tid); \
        CP_COMMIT(); } while (0)

    G1_LOAD(0, 0);
    G1_LOAD(1, 1);
    for (int c = 0; c < NC; c++) {
        if (c == NC - 1) asm volatile("cp.async.wait_group 0;" ::: "memory");
        else             asm volatile("cp.async.wait_group 1;" ::: "memory");
        __syncthreads();
        uint32_t sb = s0 + (uint32_t)(c & 1) * G1_STAGE;
        compute_fused<4, 8>(acc, sb, sb + G1_A_L, sb + G1_B_H, sb + G1_B_L, wm, wn, lane);
        __syncthreads();
        if (c + 2 < NC) G1_LOAD(c + 2, (c + 2) & 1);
    }
#undef G1_LOAD

    // epilogue: +bias, gelu, *gate, split hi/lo, store
    const float* b1e = b1p + (size_t)e * FF_;
#pragma unroll
    for (int mf = 0; mf < 4; mf++) {
#pragma unroll
        for (int h = 0; h < 2; h++) {
            int r = m0 + wm + mf * 16 + (lane >> 2) + 8 * h;
            __nv_bfloat16* rowp = g_gh + ((size_t)pair * L_ + r) * (2 * FF_);
#pragma unroll
            for (int nf = 0; nf < 8; nf++) {
                int n = n0 + wn + nf * 8 + (lane & 3) * 2;
                float v0 = acc[mf][nf][2 * h + 0] + __ldg(b1e + n);
                float v1 = acc[mf][nf][2 * h + 1] + __ldg(b1e + n + 1);
                v0 = gelu_exact(v0) * g;
                v1 = gelu_exact(v1) * g;
                __nv_bfloat16 h0 = __float2bfloat16(v0), h1 = __float2bfloat16(v1);
                __nv_bfloat162 hv; hv.x = h0; hv.y = h1;
                __nv_bfloat162 lv;
                lv.x = __float2bfloat16(v0 - __bfloat162float(h0));
                lv.y = __float2bfloat16(v1 - __bfloat162float(h1));
                *(__nv_bfloat162*)(rowp + n)       = hv;
                *(__nv_bfloat162*)(rowp + FF_ + n) = lv;
            }
        }
    }
}

// ---------------------------------------------------------------------------
// GEMM2 (R9 measured-best config): out[b] = sum_slot (g*h)[b,slot] @ W2[e_slot] + bias
// BM=128, BN=64, kc=64; stage 48KB; 2 stages (96KB) -> 2 CTAs/SM.
// 256 threads, 8 warps 4x2, warp tile 32x32. Grid (8,2,32) = 512 CTAs.
// ---------------------------------------------------------------------------
#define H2_STAGE  49152u
#define H2_A_L    16384u
#define H2_B_H    32768u
#define H2_B_L    40960u
#define H2_SMEM   (2 * 49152)

__global__ void __launch_bounds__(256, 2)
gemm2_mma(const float* __restrict__ b2p, float* __restrict__ out) {
    extern __shared__ __align__(128) char smem[];
    const int tid = threadIdx.x, lane = tid & 31, wid = tid >> 5;
    const int bb = blockIdx.z;
    const int m0 = blockIdx.y * 128, n0 = blockIdx.x * 64;
    const int e0 = g_pair_e[2 * bb + 0], e1 = g_pair_e[2 * bb + 1];
    const float g0 = g_pair_g[2 * bb + 0], g1 = g_pair_g[2 * bb + 1];

    const __nv_bfloat16* Ab[2] = {
        g_gh + ((size_t)(2 * bb + 0) * L_ + m0) * (2 * FF_),
        g_gh + ((size_t)(2 * bb + 1) * L_ + m0) * (2 * FF_)
    };
    const __nv_bfloat16* Bb[2] = {
        g_w2t + ((size_t)e0 * DM_ + n0) * (2 * FF_),
        g_w2t + ((size_t)e1 * DM_ + n0) * (2 * FF_)
    };

    uint32_t s0 = smem_u32(smem);
    const int wm = (wid >> 1) * 32, wn = (wid & 1) * 32;   // warp tile 32x32

    float acc[2][4][4] = {};
    const int NC = 64;   // 2 slots * (2048/64)

#define G2_LOAD(c, buf) do { \
        int _sl = (c) >> 5; int _k = ((c) & 31) * 64; uint32_t _d = s0 + (buf) * H2_STAGE; \
        load_tile<128, 256>(_d,          Ab[_sl] + _k,       2 * FF_, tid); \
        load_tile<128, 256>(_d + H2_A_L, Ab[_sl] + FF_ + _k, 2 * FF_, tid); \
        load_tile<64, 256> (_d + H2_B_H, Bb[_sl] + _k,       2 * FF_, tid); \
        load_tile<64, 256> (_d + H2_B_L, Bb[_sl] + FF_ + _k, 2 * FF_, tid); \
        CP_COMMIT(); } while (0)

    G2_LOAD(0, 0);
    G2_LOAD(1, 1);
    for (int c = 0; c < NC; c++) {
        if (c == NC - 1) asm volatile("cp.async.wait_group 0;" ::: "memory");
        else             asm volatile("cp.async.wait_group 1;" ::: "memory");
        __syncthreads();
        uint32_t sb = s0 + (uint32_t)(c & 1) * H2_STAGE;
        compute_fused<2, 4>(acc, sb, sb + H2_A_L, sb + H2_B_H, sb + H2_B_L, wm, wn, lane);
        __syncthreads();
        if (c + 2 < NC) G2_LOAD(c + 2, (c + 2) & 1);
    }
#undef G2_LOAD

    const float* b2e0 = b2p + (size_t)e0 * DM_;
    const float* b2e1 = b2p + (size_t)e1 * DM_;
#pragma unroll
    for (int mf = 0; mf < 2; mf++) {
#pragma unroll
        for (int h = 0; h < 2; h++) {
            int r = m0 + wm + mf * 16 + (lane >> 2) + 8 * h;
            float* op = out + ((size_t)bb * L_ + r) * DM_;
#pragma unroll
            for (int nf = 0; nf < 4; nf++) {
                int n = n0 + wn + nf * 8 + (lane & 3) * 2;
                float2 v;
                v.x = acc[mf][nf][2 * h + 0] + g0 * __ldg(b2e0 + n)     + g1 * __ldg(b2e1 + n);
                v.y = acc[mf][nf][2 * h + 1] + g0 * __ldg(b2e0 + n + 1) + g1 * __ldg(b2e1 + n + 1);
                *(float2*)(op + n) = v;
            }
        }
    }
}

// ---------------------------------------------------------------------------
// launch — kernel launches + idempotent attribute opt-ins (no statics)
// ---------------------------------------------------------------------------
extern "C" void kernel_launch(void* const* d_in, const int* in_sizes, int n_in,
                              void* d_out, int out_size) {
    const float* x      = (const float*)d_in[0];
    const float* logits = (const float*)d_in[1];
    const int*   masks  = (const int*)  d_in[2];
    const float* W1     = (const float*)d_in[3];
    const float* b1     = (const float*)d_in[4];
    const float* W2     = (const float*)d_in[5];
    const float* b2     = (const float*)d_in[6];
    float* out = (float*)d_out;

    cudaFuncSetAttribute(gemm1_mma, cudaFuncAttributeMaxDynamicSharedMemorySize, G1_SMEM);
    cudaFuncSetAttribute(gemm2_mma, cudaFuncAttributeMaxDynamicSharedMemorySize, H2_SMEM);

    prep_kernel<<<20481, 256>>>(x, logits, masks, W1, W2);

    gemm1_mma<<<dim3(FF_ / 256, L_ / 128, NPAIR), 256, G1_SMEM>>>(b1);
    gemm2_mma<<<dim3(DM_ / 64, L_ / 128, B_), 256, H2_SMEM>>>(b2, out);
}

// round 13
// speedup vs baseline: 3.6941x; 1.3287x over previous
#include <cuda_runtime.h>
#include <cuda_fp16.h>
#include <math.h>
#include <stdint.h>

#define B_   32
#define L_   256
#define DM_  512
#define FF_  2048
#define E_   8
#define NPAIR 64

// ---------------- device scratch (static = allocation-free) ----------------
__device__ int   g_pair_e[NPAIR];
__device__ float g_pair_g[NPAIR];
// x split (fp16 2-limb): [B*L][2*DM]  row = [hi | lo]
__device__ __align__(256) __half g_x2[(size_t)B_ * L_ * 2 * DM_];
// W1^T single fp16: [E][FF][DM]
__device__ __align__(256) __half g_w1t[(size_t)E_ * FF_ * DM_];
// W2^T single fp16: [E][DM][FF]
__device__ __align__(256) __half g_w2t[(size_t)E_ * DM_ * FF_];
// g*gelu(h) split (fp16 2-limb): [pair][L][2*FF]
__device__ __align__(256) __half g_gh[(size_t)NPAIR * L_ * 2 * FF_];

// ---------------- helpers ----------------
__device__ __forceinline__ uint32_t smem_u32(const void* p) {
    uint32_t a;
    asm("{ .reg .u64 t; cvta.to.shared.u64 t, %1; cvt.u32.u64 %0, t; }" : "=r"(a) : "l"(p));
    return a;
}
__device__ __forceinline__ void cp16(uint32_t dst, const void* src) {
    asm volatile("cp.async.cg.shared.global [%0], [%1], 16;" :: "r"(dst), "l"(src));
}
#define CP_COMMIT() asm volatile("cp.async.commit_group;" ::: "memory")

__device__ __forceinline__ void ldsm_x4(uint32_t& r0, uint32_t& r1, uint32_t& r2, uint32_t& r3, uint32_t a) {
    asm volatile("ldmatrix.sync.aligned.m8n8.x4.shared.b16 {%0,%1,%2,%3}, [%4];"
                 : "=r"(r0), "=r"(r1), "=r"(r2), "=r"(r3) : "r"(a));
}
__device__ __forceinline__ void mma_f16(float* c, const uint32_t* a, uint32_t b0, uint32_t b1) {
    asm volatile("mma.sync.aligned.m16n8k16.row.col.f32.f16.f16.f32 "
                 "{%0,%1,%2,%3}, {%4,%5,%6,%7}, {%8,%9}, {%0,%1,%2,%3};"
                 : "+f"(c[0]), "+f"(c[1]), "+f"(c[2]), "+f"(c[3])
                 : "r"(a[0]), "r"(a[1]), "r"(a[2]), "r"(a[3]), "r"(b0), "r"(b1));
}
__device__ __forceinline__ float gelu_exact(float x) {
    return 0.5f * x * (1.0f + erff(x * 0.70710678118654752440f));
}

// Load a ROWS x 64 fp16 tile (128B rows, XOR swizzle chunk^=(row&7)) via cp.async.
template<int ROWS, int NT>
__device__ __forceinline__ void load_tile(uint32_t dst, const __half* src, int ld, int tid) {
    constexpr int ITER = ROWS * 8 / NT;
#pragma unroll
    for (int j = 0; j < ITER; j++) {
        int idx = tid + j * NT;
        int r = idx >> 3, c = idx & 7;
        uint32_t off = (uint32_t)(r * 128 + ((c ^ (r & 7)) * 16));
        cp16(dst + off, (const char*)src + (size_t)r * ld * 2 + c * 16);
    }
}

// 2-term fused chunk: load Ah/Al/B fragments once; acc += Ah*B + Al*B.
template<int MF, int NF>
__device__ __forceinline__ void compute_fused2(float (&acc)[MF][NF][4],
                                               uint32_t aH, uint32_t aL, uint32_t bB,
                                               int wm, int wn, int lane) {
#pragma unroll
    for (int ks = 0; ks < 4; ks++) {
        uint32_t ah[MF][4], al[MF][4];
#pragma unroll
        for (int mf = 0; mf < MF; mf++) {
            int r = wm + mf * 16 + (lane & 15);
            int c = ks * 2 + (lane >> 4);
            uint32_t off = (uint32_t)(r * 128 + ((c ^ (r & 7)) * 16));
            ldsm_x4(ah[mf][0], ah[mf][1], ah[mf][2], ah[mf][3], aH + off);
            ldsm_x4(al[mf][0], al[mf][1], al[mf][2], al[mf][3], aL + off);
        }
#pragma unroll
        for (int nfp = 0; nfp < NF / 2; nfp++) {
            int q = lane >> 3;
            int r = wn + (nfp * 2 + (q >> 1)) * 8 + (lane & 7);
            int c = ks * 2 + (q & 1);
            uint32_t off = (uint32_t)(r * 128 + ((c ^ (r & 7)) * 16));
            uint32_t b0, b1, b2, b3;
            ldsm_x4(b0, b1, b2, b3, bB + off);
#pragma unroll
            for (int mf = 0; mf < MF; mf++) {
                mma_f16(acc[mf][2 * nfp],     ah[mf], b0, b1);
                mma_f16(acc[mf][2 * nfp + 1], ah[mf], b2, b3);
                mma_f16(acc[mf][2 * nfp],     al[mf], b0, b1);
                mma_f16(acc[mf][2 * nfp + 1], al[mf], b2, b3);
            }
        }
    }
}

// ---------------------------------------------------------------------------
// Fused prep: gates + x fp16-limb split (float4) + W1^T fp16 + W2^T fp16.
//   [0, 4096)       : x split (1024 elems per block, float4)
//   [4096, 12288)   : W1 transpose tiles (64 x 16 x 8)
//   [12288, 20480)  : W2 transpose tiles (16 x 64 x 8)
//   [20480]         : gates (first 32 threads)
// ---------------------------------------------------------------------------
__device__ __forceinline__ void transpose_sec(const float* __restrict__ W,
                                              __half* __restrict__ T,
                                              int K, int N, int bx, int by, int bz,
                                              int tx, int ty, float (*s)[33]) {
    int n0 = bx * 32, k0 = by * 32;
    const float* Wp = W + (size_t)bz * K * N;
#pragma unroll
    for (int i = 0; i < 32; i += 8)
        s[ty + i][tx] = Wp[(size_t)(k0 + ty + i) * N + n0 + tx];
    __syncthreads();
#pragma unroll
    for (int i = 0; i < 32; i += 8) {
        int n = n0 + ty + i;
        int k = k0 + tx;
        T[((size_t)bz * N + n) * K + k] = __float2half(s[tx][ty + i]);
    }
}

__global__ void prep_kernel(const float* __restrict__ X,
                            const float* __restrict__ logits,
                            const int*   __restrict__ masks,
                            const float* __restrict__ W1,
                            const float* __restrict__ W2) {
    __shared__ float s[32][33];
    const int blk = blockIdx.x;
    const int tid = threadIdx.x;
    const int tx = tid & 31, ty = tid >> 5;

    if (blk < 4096) {
        // x split into fp16 hi/lo limbs, 4 elems/thread via float4
        size_t i4 = (size_t)blk * 256 + tid;
        size_t row = i4 / (DM_ / 4);
        int k4 = (int)(i4 % (DM_ / 4));
        float4 v = ((const float4*)X)[i4];
        float vv[4] = {v.x, v.y, v.z, v.w};
        __half hh[4], ll[4];
#pragma unroll
        for (int t = 0; t < 4; t++) {
            hh[t] = __float2half(vv[t]);
            ll[t] = __float2half(vv[t] - __half2float(hh[t]));
        }
        *(uint2*)(g_x2 + row * (2 * DM_) + k4 * 4)       = *(uint2*)hh;
        *(uint2*)(g_x2 + row * (2 * DM_) + DM_ + k4 * 4) = *(uint2*)ll;
    } else if (blk < 12288) {
        int i = blk - 4096;                        // W1: bx<64, by<16, bz<8
        transpose_sec(W1, g_w1t, DM_, FF_, i & 63, (i >> 6) & 15, i >> 10, tx, ty, s);
    } else if (blk < 20480) {
        int i = blk - 12288;                       // W2: bx<16, by<64, bz<8
        transpose_sec(W2, g_w2t, FF_, DM_, i & 15, (i >> 4) & 63, i >> 10, tx, ty, s);
    } else {
        // gates
        int b = tid;
        if (b >= B_) return;
        float p[E_];
        float mx = -1e30f;
#pragma unroll
        for (int i = 0; i < E_; i++) { p[i] = logits[b * E_ + i]; mx = fmaxf(mx, p[i]); }
        float sum = 0.0f;
#pragma unroll
        for (int i = 0; i < E_; i++) { p[i] = expf(p[i] - mx); sum += p[i]; }
        float inv = 1.0f / sum;
#pragma unroll
        for (int i = 0; i < E_; i++) p[i] = (masks[b * E_ + i] == 1) ? p[i] * inv : 0.0f;
        int i1 = 0;
#pragma unroll
        for (int i = 1; i < E_; i++) if (p[i] > p[i1]) i1 = i;
        int i2 = -1;
#pragma unroll
        for (int i = 0; i < E_; i++) {
            if (i == i1) continue;
            if (i2 < 0 || p[i] > p[i2]) i2 = i;
        }
        float denom = p[i1] + p[i2] + 1e-9f;
        g_pair_e[2 * b + 0] = i1;  g_pair_g[2 * b + 0] = p[i1] / denom;
        g_pair_e[2 * b + 1] = i2;  g_pair_g[2 * b + 1] = p[i2] / denom;
    }
}

// ---------------------------------------------------------------------------
// GEMM1 (fp16 2-term): gh[pair] = g * gelu(x[b] @ W1[e] + b1[e])
// BM=128, BN=256, kc=64; stage = Ah16+Al16+B32 = 64KB; 3 stages (192KB),
// 1 sync/iter. 256 threads, warp tile 64x64 (MF=4, NF=8). Grid (8,2,64).
// ---------------------------------------------------------------------------
#define G1_STAGE  65536u
#define G1_A_L    16384u
#define G1_B_O    32768u
#define G1_SMEM   (3 * 65536)

__global__ void __launch_bounds__(256, 1)
gemm1_mma(const float* __restrict__ b1p) {
    extern __shared__ __align__(128) char smem[];
    const int tid = threadIdx.x, lane = tid & 31, wid = tid >> 5;
    const int pair = blockIdx.z;
    const int e = g_pair_e[pair];
    const float g = g_pair_g[pair];
    const int m0 = blockIdx.y * 128, n0 = blockIdx.x * 256;

    const __half* Abase = g_x2  + ((size_t)(pair >> 1) * L_ + m0) * (2 * DM_);
    const __half* Bbase = g_w1t + ((size_t)e * FF_ + n0) * DM_;

    uint32_t s0 = smem_u32(smem);
    const int wm = (wid >> 2) * 64, wn = (wid & 3) * 64;   // warp tile 64x64

    float acc[4][8][4] = {};
    const int NC = 8;   // 512 / 64

#define G1_LOAD(c, buf) do { int _k = (c) * 64; uint32_t _d = s0 + (buf) * G1_STAGE; \
        load_tile<128, 256>(_d,          Abase + _k,       2 * DM_, tid); \
        load_tile<128, 256>(_d + G1_A_L, Abase + DM_ + _k, 2 * DM_, tid); \
        load_tile<256, 256>(_d + G1_B_O, Bbase + _k,       DM_,     tid); \
        CP_COMMIT(); } while (0)

    G1_LOAD(0, 0);
    G1_LOAD(1, 1);
    for (int c = 0; c < NC; c++) {
        if (c == NC - 1) asm volatile("cp.async.wait_group 0;" ::: "memory");
        else             asm volatile("cp.async.wait_group 1;" ::: "memory");
        __syncthreads();   // tile c visible; all warps done with buf (c+2)%3 (last read at c-1)
        if (c + 2 < NC) G1_LOAD(c + 2, (uint32_t)((c + 2) % 3));
        uint32_t sb = s0 + (uint32_t)(c % 3) * G1_STAGE;
        compute_fused2<4, 8>(acc, sb, sb + G1_A_L, sb + G1_B_O, wm, wn, lane);
    }
#undef G1_LOAD

    // epilogue: +bias, gelu, *gate, fp16 hi/lo split, store
    const float* b1e = b1p + (size_t)e * FF_;
#pragma unroll
    for (int mf = 0; mf < 4; mf++) {
#pragma unroll
        for (int h = 0; h < 2; h++) {
            int r = m0 + wm + mf * 16 + (lane >> 2) + 8 * h;
            __half* rowp = g_gh + ((size_t)pair * L_ + r) * (2 * FF_);
#pragma unroll
            for (int nf = 0; nf < 8; nf++) {
                int n = n0 + wn + nf * 8 + (lane & 3) * 2;
                float v0 = acc[mf][nf][2 * h + 0] + __ldg(b1e + n);
                float v1 = acc[mf][nf][2 * h + 1] + __ldg(b1e + n + 1);
                v0 = gelu_exact(v0) * g;
                v1 = gelu_exact(v1) * g;
                __half h0 = __float2half(v0), h1 = __float2half(v1);
                __half hv[2] = {h0, h1};
                __half lv[2] = {__float2half(v0 - __half2float(h0)),
                                __float2half(v1 - __half2float(h1))};
                *(uint32_t*)(rowp + n)       = *(uint32_t*)hv;
                *(uint32_t*)(rowp + FF_ + n) = *(uint32_t*)lv;
            }
        }
    }
}

// ---------------------------------------------------------------------------
// GEMM2 (fp16 2-term): out[b] = sum_slot (g*h)[b,slot] @ W2[e_slot] + bias
// BM=128, BN=64, kc=64; stage = Ah16+Al16+B8 = 40KB; 2 stages (80KB) -> 2 CTAs/SM.
// 256 threads, warp tile 32x32. Grid (8,2,32) = 512 CTAs. Virtual K = 2*2048.
// ---------------------------------------------------------------------------
#define H2_STAGE  40960u
#define H2_A_L    16384u
#define H2_B_O    32768u
#define H2_SMEM   (2 * 40960)

__global__ void __launch_bounds__(256, 2)
gemm2_mma(const float* __restrict__ b2p, float* __restrict__ out) {
    extern __shared__ __align__(128) char smem[];
    const int tid = threadIdx.x, lane = tid & 31, wid = tid >> 5;
    const int bb = blockIdx.z;
    const int m0 = blockIdx.y * 128, n0 = blockIdx.x * 64;
    const int e0 = g_pair_e[2 * bb + 0], e1 = g_pair_e[2 * bb + 1];
    const float g0 = g_pair_g[2 * bb + 0], g1 = g_pair_g[2 * bb + 1];

    const __half* Ab[2] = {
        g_gh + ((size_t)(2 * bb + 0) * L_ + m0) * (2 * FF_),
        g_gh + ((size_t)(2 * bb + 1) * L_ + m0) * (2 * FF_)
    };
    const __half* Bb[2] = {
        g_w2t + ((size_t)e0 * DM_ + n0) * FF_,
        g_w2t + ((size_t)e1 * DM_ + n0) * FF_
    };

    uint32_t s0 = smem_u32(smem);
    const int wm = (wid >> 1) * 32, wn = (wid & 1) * 32;   // warp tile 32x32

    float acc[2][4][4] = {};
    const int NC = 64;   // 2 slots * (2048/64)

#define G2_LOAD(c, buf) do { \
        int _sl = (c) >> 5; int _k = ((c) & 31) * 64; uint32_t _d = s0 + (buf) * H2_STAGE; \
        load_tile<128, 256>(_d,          Ab[_sl] + _k,       2 * FF_, tid); \
        load_tile<128, 256>(_d + H2_A_L, Ab[_sl] + FF_ + _k, 2 * FF_, tid); \
        load_tile<64, 256> (_d + H2_B_O, Bb[_sl] + _k,       FF_,     tid); \
        CP_COMMIT(); } while (0)

    G2_LOAD(0, 0);
    G2_LOAD(1, 1);
    for (int c = 0; c < NC; c++) {
        if (c == NC - 1) asm volatile("cp.async.wait_group 0;" ::: "memory");
        else             asm volatile("cp.async.wait_group 1;" ::: "memory");
        __syncthreads();
        uint32_t sb = s0 + (uint32_t)(c & 1) * H2_STAGE;
        compute_fused2<2, 4>(acc, sb, sb + H2_A_L, sb + H2_B_O, wm, wn, lane);
        __syncthreads();
        if (c + 2 < NC) G2_LOAD(c + 2, (c + 2) & 1);
    }
#undef G2_LOAD

    const float* b2e0 = b2p + (size_t)e0 * DM_;
    const float* b2e1 = b2p + (size_t)e1 * DM_;
#pragma unroll
    for (int mf = 0; mf < 2; mf++) {
#pragma unroll
        for (int h = 0; h < 2; h++) {
            int r = m0 + wm + mf * 16 + (lane >> 2) + 8 * h;
            float* op = out + ((size_t)bb * L_ + r) * DM_;
#pragma unroll
            for (int nf = 0; nf < 4; nf++) {
                int n = n0 + wn + nf * 8 + (lane & 3) * 2;
                float2 v;
                v.x = acc[mf][nf][2 * h + 0] + g0 * __ldg(b2e0 + n)     + g1 * __ldg(b2e1 + n);
                v.y = acc[mf][nf][2 * h + 1] + g0 * __ldg(b2e0 + n + 1) + g1 * __ldg(b2e1 + n + 1);
                *(float2*)(op + n) = v;
            }
        }
    }
}

// ---------------------------------------------------------------------------
// launch — kernel launches + idempotent attribute opt-ins (no statics)
// ---------------------------------------------------------------------------
extern "C" void kernel_launch(void* const* d_in, const int* in_sizes, int n_in,
                              void* d_out, int out_size) {
    const float* x      = (const float*)d_in[0];
    const float* logits = (const float*)d_in[1];
    const int*   masks  = (const int*)  d_in[2];
    const float* W1     = (const float*)d_in[3];
    const float* b1     = (const float*)d_in[4];
    const float* W2     = (const float*)d_in[5];
    const float* b2     = (const float*)d_in[6];
    float* out = (float*)d_out;

    cudaFuncSetAttribute(gemm1_mma, cudaFuncAttributeMaxDynamicSharedMemorySize, G1_SMEM);
    cudaFuncSetAttribute(gemm2_mma, cudaFuncAttributeMaxDynamicSharedMemorySize, H2_SMEM);

    prep_kernel<<<20481, 256>>>(x, logits, masks, W1, W2);

    gemm1_mma<<<dim3(FF_ / 256, L_ / 128, NPAIR), 256, G1_SMEM>>>(b1);
    gemm2_mma<<<dim3(DM_ / 64, L_ / 128, B_), 256, H2_SMEM>>>(b2, out);
}

// round 14
// speedup vs baseline: 4.7765x; 1.2930x over previous
#include <cuda_runtime.h>
#include <cuda_fp16.h>
#include <math.h>
#include <stdint.h>

#define B_   32
#define L_   256
#define DM_  512
#define FF_  2048
#define E_   8
#define NPAIR 64

// ---------------- device scratch (static = allocation-free) ----------------
__device__ int   g_pair_e[NPAIR];
__device__ float g_pair_g[NPAIR];
// x split (fp16 2-limb): [B*L][2*DM]  row = [hi | lo]
__device__ __align__(256) __half g_x2[(size_t)B_ * L_ * 2 * DM_];
// W1^T single fp16: [E][FF][DM]
__device__ __align__(256) __half g_w1t[(size_t)E_ * FF_ * DM_];
// W2^T single fp16: [E][DM][FF]
__device__ __align__(256) __half g_w2t[(size_t)E_ * DM_ * FF_];
// g*gelu(h) SINGLE fp16: [pair][L][FF]
__device__ __align__(256) __half g_gh[(size_t)NPAIR * L_ * FF_];

// ---------------- helpers ----------------
__device__ __forceinline__ uint32_t smem_u32(const void* p) {
    uint32_t a;
    asm("{ .reg .u64 t; cvta.to.shared.u64 t, %1; cvt.u32.u64 %0, t; }" : "=r"(a) : "l"(p));
    return a;
}
__device__ __forceinline__ void cp16(uint32_t dst, const void* src) {
    asm volatile("cp.async.cg.shared.global [%0], [%1], 16;" :: "r"(dst), "l"(src));
}
#define CP_COMMIT() asm volatile("cp.async.commit_group;" ::: "memory")

__device__ __forceinline__ void ldsm_x4(uint32_t& r0, uint32_t& r1, uint32_t& r2, uint32_t& r3, uint32_t a) {
    asm volatile("ldmatrix.sync.aligned.m8n8.x4.shared.b16 {%0,%1,%2,%3}, [%4];"
                 : "=r"(r0), "=r"(r1), "=r"(r2), "=r"(r3) : "r"(a));
}
__device__ __forceinline__ void mma_f16(float* c, const uint32_t* a, uint32_t b0, uint32_t b1) {
    asm volatile("mma.sync.aligned.m16n8k16.row.col.f32.f16.f16.f32 "
                 "{%0,%1,%2,%3}, {%4,%5,%6,%7}, {%8,%9}, {%0,%1,%2,%3};"
                 : "+f"(c[0]), "+f"(c[1]), "+f"(c[2]), "+f"(c[3])
                 : "r"(a[0]), "r"(a[1]), "r"(a[2]), "r"(a[3]), "r"(b0), "r"(b1));
}
__device__ __forceinline__ float gelu_exact(float x) {
    return 0.5f * x * (1.0f + erff(x * 0.70710678118654752440f));
}

// Load a ROWS x 64 fp16 tile (128B rows, XOR swizzle chunk^=(row&7)) via cp.async.
template<int ROWS, int NT>
__device__ __forceinline__ void load_tile(uint32_t dst, const __half* src, int ld, int tid) {
    constexpr int ITER = ROWS * 8 / NT;
#pragma unroll
    for (int j = 0; j < ITER; j++) {
        int idx = tid + j * NT;
        int r = idx >> 3, c = idx & 7;
        uint32_t off = (uint32_t)(r * 128 + ((c ^ (r & 7)) * 16));
        cp16(dst + off, (const char*)src + (size_t)r * ld * 2 + c * 16);
    }
}

// 2-term fused chunk: load Ah/Al/B fragments once; acc += Ah*B + Al*B.
template<int MF, int NF>
__device__ __forceinline__ void compute_fused2(float (&acc)[MF][NF][4],
                                               uint32_t aH, uint32_t aL, uint32_t bB,
                                               int wm, int wn, int lane) {
#pragma unroll
    for (int ks = 0; ks < 4; ks++) {
        uint32_t ah[MF][4], al[MF][4];
#pragma unroll
        for (int mf = 0; mf < MF; mf++) {
            int r = wm + mf * 16 + (lane & 15);
            int c = ks * 2 + (lane >> 4);
            uint32_t off = (uint32_t)(r * 128 + ((c ^ (r & 7)) * 16));
            ldsm_x4(ah[mf][0], ah[mf][1], ah[mf][2], ah[mf][3], aH + off);
            ldsm_x4(al[mf][0], al[mf][1], al[mf][2], al[mf][3], aL + off);
        }
#pragma unroll
        for (int nfp = 0; nfp < NF / 2; nfp++) {
            int q = lane >> 3;
            int r = wn + (nfp * 2 + (q >> 1)) * 8 + (lane & 7);
            int c = ks * 2 + (q & 1);
            uint32_t off = (uint32_t)(r * 128 + ((c ^ (r & 7)) * 16));
            uint32_t b0, b1, b2, b3;
            ldsm_x4(b0, b1, b2, b3, bB + off);
#pragma unroll
            for (int mf = 0; mf < MF; mf++) {
                mma_f16(acc[mf][2 * nfp],     ah[mf], b0, b1);
                mma_f16(acc[mf][2 * nfp + 1], ah[mf], b2, b3);
                mma_f16(acc[mf][2 * nfp],     al[mf], b0, b1);
                mma_f16(acc[mf][2 * nfp + 1], al[mf], b2, b3);
            }
        }
    }
}

// 1-term chunk: acc += A*B.
template<int MF, int NF>
__device__ __forceinline__ void compute_single(float (&acc)[MF][NF][4],
                                               uint32_t aA, uint32_t bB,
                                               int wm, int wn, int lane) {
#pragma unroll
    for (int ks = 0; ks < 4; ks++) {
        uint32_t af[MF][4];
#pragma unroll
        for (int mf = 0; mf < MF; mf++) {
            int r = wm + mf * 16 + (lane & 15);
            int c = ks * 2 + (lane >> 4);
            uint32_t off = (uint32_t)(r * 128 + ((c ^ (r & 7)) * 16));
            ldsm_x4(af[mf][0], af[mf][1], af[mf][2], af[mf][3], aA + off);
        }
#pragma unroll
        for (int nfp = 0; nfp < NF / 2; nfp++) {
            int q = lane >> 3;
            int r = wn + (nfp * 2 + (q >> 1)) * 8 + (lane & 7);
            int c = ks * 2 + (q & 1);
            uint32_t off = (uint32_t)(r * 128 + ((c ^ (r & 7)) * 16));
            uint32_t b0, b1, b2, b3;
            ldsm_x4(b0, b1, b2, b3, bB + off);
#pragma unroll
            for (int mf = 0; mf < MF; mf++) {
                mma_f16(acc[mf][2 * nfp],     af[mf], b0, b1);
                mma_f16(acc[mf][2 * nfp + 1], af[mf], b2, b3);
            }
        }
    }
}

// ---------------------------------------------------------------------------
// Fused prep: gates + x fp16-limb split (float4) + W1^T fp16 + W2^T fp16.
// ---------------------------------------------------------------------------
__device__ __forceinline__ void transpose_sec(const float* __restrict__ W,
                                              __half* __restrict__ T,
                                              int K, int N, int bx, int by, int bz,
                                              int tx, int ty, float (*s)[33]) {
    int n0 = bx * 32, k0 = by * 32;
    const float* Wp = W + (size_t)bz * K * N;
#pragma unroll
    for (int i = 0; i < 32; i += 8)
        s[ty + i][tx] = Wp[(size_t)(k0 + ty + i) * N + n0 + tx];
    __syncthreads();
#pragma unroll
    for (int i = 0; i < 32; i += 8) {
        int n = n0 + ty + i;
        int k = k0 + tx;
        T[((size_t)bz * N + n) * K + k] = __float2half(s[tx][ty + i]);
    }
}

__global__ void prep_kernel(const float* __restrict__ X,
                            const float* __restrict__ logits,
                            const int*   __restrict__ masks,
                            const float* __restrict__ W1,
                            const float* __restrict__ W2) {
    __shared__ float s[32][33];
    const int blk = blockIdx.x;
    const int tid = threadIdx.x;
    const int tx = tid & 31, ty = tid >> 5;

    if (blk < 4096) {
        // x split into fp16 hi/lo limbs, 4 elems/thread via float4
        size_t i4 = (size_t)blk * 256 + tid;
        size_t row = i4 / (DM_ / 4);
        int k4 = (int)(i4 % (DM_ / 4));
        float4 v = ((const float4*)X)[i4];
        float vv[4] = {v.x, v.y, v.z, v.w};
        __half hh[4], ll[4];
#pragma unroll
        for (int t = 0; t < 4; t++) {
            hh[t] = __float2half(vv[t]);
            ll[t] = __float2half(vv[t] - __half2float(hh[t]));
        }
        *(uint2*)(g_x2 + row * (2 * DM_) + k4 * 4)       = *(uint2*)hh;
        *(uint2*)(g_x2 + row * (2 * DM_) + DM_ + k4 * 4) = *(uint2*)ll;
    } else if (blk < 12288) {
        int i = blk - 4096;                        // W1: bx<64, by<16, bz<8
        transpose_sec(W1, g_w1t, DM_, FF_, i & 63, (i >> 6) & 15, i >> 10, tx, ty, s);
    } else if (blk < 20480) {
        int i = blk - 12288;                       // W2: bx<16, by<64, bz<8
        transpose_sec(W2, g_w2t, FF_, DM_, i & 15, (i >> 4) & 63, i >> 10, tx, ty, s);
    } else {
        // gates
        int b = tid;
        if (b >= B_) return;
        float p[E_];
        float mx = -1e30f;
#pragma unroll
        for (int i = 0; i < E_; i++) { p[i] = logits[b * E_ + i]; mx = fmaxf(mx, p[i]); }
        float sum = 0.0f;
#pragma unroll
        for (int i = 0; i < E_; i++) { p[i] = expf(p[i] - mx); sum += p[i]; }
        float inv = 1.0f / sum;
#pragma unroll
        for (int i = 0; i < E_; i++) p[i] = (masks[b * E_ + i] == 1) ? p[i] * inv : 0.0f;
        int i1 = 0;
#pragma unroll
        for (int i = 1; i < E_; i++) if (p[i] > p[i1]) i1 = i;
        int i2 = -1;
#pragma unroll
        for (int i = 0; i < E_; i++) {
            if (i == i1) continue;
            if (i2 < 0 || p[i] > p[i2]) i2 = i;
        }
        float denom = p[i1] + p[i2] + 1e-9f;
        g_pair_e[2 * b + 0] = i1;  g_pair_g[2 * b + 0] = p[i1] / denom;
        g_pair_e[2 * b + 1] = i2;  g_pair_g[2 * b + 1] = p[i2] / denom;
    }
}

// ---------------------------------------------------------------------------
// GEMM1 (fp16 2-term): gh[pair] = fp16( g * gelu(x[b] @ W1[e] + b1[e]) )
// BM=128, BN=256, kc=64; stage = Ah16+Al16+B32 = 64KB; 3 stages (192KB),
// 1 sync/iter. 256 threads, warp tile 64x64 (MF=4, NF=8). Grid (8,2,64).
// ---------------------------------------------------------------------------
#define G1_STAGE  65536u
#define G1_A_L    16384u
#define G1_B_O    32768u
#define G1_SMEM   (3 * 65536)

__global__ void __launch_bounds__(256, 1)
gemm1_mma(const float* __restrict__ b1p) {
    extern __shared__ __align__(128) char smem[];
    const int tid = threadIdx.x, lane = tid & 31, wid = tid >> 5;
    const int pair = blockIdx.z;
    const int e = g_pair_e[pair];
    const float g = g_pair_g[pair];
    const int m0 = blockIdx.y * 128, n0 = blockIdx.x * 256;

    const __half* Abase = g_x2  + ((size_t)(pair >> 1) * L_ + m0) * (2 * DM_);
    const __half* Bbase = g_w1t + ((size_t)e * FF_ + n0) * DM_;

    uint32_t s0 = smem_u32(smem);
    const int wm = (wid >> 2) * 64, wn = (wid & 3) * 64;   // warp tile 64x64

    float acc[4][8][4] = {};
    const int NC = 8;   // 512 / 64

#define G1_LOAD(c, buf) do { int _k = (c) * 64; uint32_t _d = s0 + (buf) * G1_STAGE; \
        load_tile<128, 256>(_d,          Abase + _k,       2 * DM_, tid); \
        load_tile<128, 256>(_d + G1_A_L, Abase + DM_ + _k, 2 * DM_, tid); \
        load_tile<256, 256>(_d + G1_B_O, Bbase + _k,       DM_,     tid); \
        CP_COMMIT(); } while (0)

    G1_LOAD(0, 0);
    G1_LOAD(1, 1);
    for (int c = 0; c < NC; c++) {
        if (c == NC - 1) asm volatile("cp.async.wait_group 0;" ::: "memory");
        else             asm volatile("cp.async.wait_group 1;" ::: "memory");
        __syncthreads();
        if (c + 2 < NC) G1_LOAD(c + 2, (uint32_t)((c + 2) % 3));
        uint32_t sb = s0 + (uint32_t)(c % 3) * G1_STAGE;
        compute_fused2<4, 8>(acc, sb, sb + G1_A_L, sb + G1_B_O, wm, wn, lane);
    }
#undef G1_LOAD

    // epilogue: +bias, gelu, *gate, store single fp16
    const float* b1e = b1p + (size_t)e * FF_;
#pragma unroll
    for (int mf = 0; mf < 4; mf++) {
#pragma unroll
        for (int h = 0; h < 2; h++) {
            int r = m0 + wm + mf * 16 + (lane >> 2) + 8 * h;
            __half* rowp = g_gh + ((size_t)pair * L_ + r) * FF_;
#pragma unroll
            for (int nf = 0; nf < 8; nf++) {
                int n = n0 + wn + nf * 8 + (lane & 3) * 2;
                float v0 = acc[mf][nf][2 * h + 0] + __ldg(b1e + n);
                float v1 = acc[mf][nf][2 * h + 1] + __ldg(b1e + n + 1);
                __half hv[2] = {__float2half(gelu_exact(v0) * g),
                                __float2half(gelu_exact(v1) * g)};
                *(uint32_t*)(rowp + n) = *(uint32_t*)hv;
            }
        }
    }
}

// ---------------------------------------------------------------------------
// GEMM2 (fp16 1-term): out[b] = sum_slot gh[b,slot] @ W2[e_slot] + gated bias
// BM=128, BN=64, kc=64; stage = A16+B8 = 24KB; 3 stages (72KB) -> 2 CTAs/SM.
// 256 threads, 8 warps 4x2, warp tile 32x32. Grid (8,2,32) = 512 CTAs.
// Virtual K = 2 slots * 2048 (64 chunks); 1 sync/iter.
// ---------------------------------------------------------------------------
#define H2_STAGE  24576u
#define H2_B_O    16384u
#define H2_SMEM   (3 * 24576)

__global__ void __launch_bounds__(256, 2)
gemm2_mma(const float* __restrict__ b2p, float* __restrict__ out) {
    extern __shared__ __align__(128) char smem[];
    const int tid = threadIdx.x, lane = tid & 31, wid = tid >> 5;
    const int bb = blockIdx.z;
    const int m0 = blockIdx.y * 128, n0 = blockIdx.x * 64;
    const int e0 = g_pair_e[2 * bb + 0], e1 = g_pair_e[2 * bb + 1];
    const float g0 = g_pair_g[2 * bb + 0], g1 = g_pair_g[2 * bb + 1];

    const __half* Ab[2] = {
        g_gh + ((size_t)(2 * bb + 0) * L_ + m0) * FF_,
        g_gh + ((size_t)(2 * bb + 1) * L_ + m0) * FF_
    };
    const __half* Bb[2] = {
        g_w2t + ((size_t)e0 * DM_ + n0) * FF_,
        g_w2t + ((size_t)e1 * DM_ + n0) * FF_
    };

    uint32_t s0 = smem_u32(smem);
    const int wm = (wid >> 1) * 32, wn = (wid & 1) * 32;   // warp tile 32x32

    float acc[2][4][4] = {};
    const int NC = 64;   // 2 slots * (2048/64)

#define G2_LOAD(c, buf) do { \
        int _sl = (c) >> 5; int _k = ((c) & 31) * 64; uint32_t _d = s0 + (buf) * H2_STAGE; \
        load_tile<128, 256>(_d,          Ab[_sl] + _k, FF_, tid); \
        load_tile<64, 256> (_d + H2_B_O, Bb[_sl] + _k, FF_, tid); \
        CP_COMMIT(); } while (0)

    G2_LOAD(0, 0);
    G2_LOAD(1, 1);
    for (int c = 0; c < NC; c++) {
        if (c == NC - 1) asm volatile("cp.async.wait_group 0;" ::: "memory");
        else             asm volatile("cp.async.wait_group 1;" ::: "memory");
        __syncthreads();
        if (c + 2 < NC) G2_LOAD(c + 2, (uint32_t)((c + 2) % 3));
        uint32_t sb = s0 + (uint32_t)(c % 3) * H2_STAGE;
        compute_single<2, 4>(acc, sb, sb + H2_B_O, wm, wn, lane);
    }
#undef G2_LOAD

    const float* b2e0 = b2p + (size_t)e0 * DM_;
    const float* b2e1 = b2p + (size_t)e1 * DM_;
#pragma unroll
    for (int mf = 0; mf < 2; mf++) {
#pragma unroll
        for (int h = 0; h < 2; h++) {
            int r = m0 + wm + mf * 16 + (lane >> 2) + 8 * h;
            float* op = out + ((size_t)bb * L_ + r) * DM_;
#pragma unroll
            for (int nf = 0; nf < 4; nf++) {
                int n = n0 + wn + nf * 8 + (lane & 3) * 2;
                float2 v;
                v.x = acc[mf][nf][2 * h + 0] + g0 * __ldg(b2e0 + n)     + g1 * __ldg(b2e1 + n);
                v.y = acc[mf][nf][2 * h + 1] + g0 * __ldg(b2e0 + n + 1) + g1 * __ldg(b2e1 + n + 1);
                *(float2*)(op + n) = v;
            }
        }
    }
}

// ---------------------------------------------------------------------------
// launch — kernel launches + idempotent attribute opt-ins (no statics)
// ---------------------------------------------------------------------------
extern "C" void kernel_launch(void* const* d_in, const int* in_sizes, int n_in,
                              void* d_out, int out_size) {
    const float* x      = (const float*)d_in[0];
    const float* logits = (const float*)d_in[1];
    const int*   masks  = (const int*)  d_in[2];
    const float* W1     = (const float*)d_in[3];
    const float* b1     = (const float*)d_in[4];
    const float* W2     = (const float*)d_in[5];
    const float* b2     = (const float*)d_in[6];
    float* out = (float*)d_out;

    cudaFuncSetAttribute(gemm1_mma, cudaFuncAttributeMaxDynamicSharedMemorySize, G1_SMEM);
    cudaFuncSetAttribute(gemm2_mma, cudaFuncAttributeMaxDynamicSharedMemorySize, H2_SMEM);

    prep_kernel<<<20481, 256>>>(x, logits, masks, W1, W2);

    gemm1_mma<<<dim3(FF_ / 256, L_ / 128, NPAIR), 256, G1_SMEM>>>(b1);
    gemm2_mma<<<dim3(DM_ / 64, L_ / 128, B_), 256, H2_SMEM>>>(b2, out);
}

// round 15
// speedup vs baseline: 5.9905x; 1.2542x over previous
#include <cuda_runtime.h>
#include <cuda_fp16.h>
#include <math.h>
#include <stdint.h>

#define B_   32
#define L_   256
#define DM_  512
#define FF_  2048
#define E_   8
#define NPAIR 64

// ---------------- device scratch (static = allocation-free) ----------------
__device__ int   g_pair_e[NPAIR];
__device__ float g_pair_g[NPAIR];
// x single fp16: [B*L][DM]
__device__ __align__(256) __half g_x[(size_t)B_ * L_ * DM_];
// W1^T single fp16: [E][FF][DM]
__device__ __align__(256) __half g_w1t[(size_t)E_ * FF_ * DM_];
// W2^T single fp16: [E][DM][FF]
__device__ __align__(256) __half g_w2t[(size_t)E_ * DM_ * FF_];
// g*gelu(h) single fp16: [pair][L][FF]
__device__ __align__(256) __half g_gh[(size_t)NPAIR * L_ * FF_];

// ---------------- helpers ----------------
__device__ __forceinline__ uint32_t smem_u32(const void* p) {
    uint32_t a;
    asm("{ .reg .u64 t; cvta.to.shared.u64 t, %1; cvt.u32.u64 %0, t; }" : "=r"(a) : "l"(p));
    return a;
}
__device__ __forceinline__ void cp16(uint32_t dst, const void* src) {
    asm volatile("cp.async.cg.shared.global [%0], [%1], 16;" :: "r"(dst), "l"(src));
}
#define CP_COMMIT() asm volatile("cp.async.commit_group;" ::: "memory")

__device__ __forceinline__ void ldsm_x4(uint32_t& r0, uint32_t& r1, uint32_t& r2, uint32_t& r3, uint32_t a) {
    asm volatile("ldmatrix.sync.aligned.m8n8.x4.shared.b16 {%0,%1,%2,%3}, [%4];"
                 : "=r"(r0), "=r"(r1), "=r"(r2), "=r"(r3) : "r"(a));
}
__device__ __forceinline__ void mma_f16(float* c, const uint32_t* a, uint32_t b0, uint32_t b1) {
    asm volatile("mma.sync.aligned.m16n8k16.row.col.f32.f16.f16.f32 "
                 "{%0,%1,%2,%3}, {%4,%5,%6,%7}, {%8,%9}, {%0,%1,%2,%3};"
                 : "+f"(c[0]), "+f"(c[1]), "+f"(c[2]), "+f"(c[3])
                 : "r"(a[0]), "r"(a[1]), "r"(a[2]), "r"(a[3]), "r"(b0), "r"(b1));
}
__device__ __forceinline__ float gelu_exact(float x) {
    return 0.5f * x * (1.0f + erff(x * 0.70710678118654752440f));
}

// Load a ROWS x 64 fp16 tile (128B rows, XOR swizzle chunk^=(row&7)) via cp.async.
template<int ROWS, int NT>
__device__ __forceinline__ void load_tile(uint32_t dst, const __half* src, int ld, int tid) {
    constexpr int ITER = ROWS * 8 / NT;
#pragma unroll
    for (int j = 0; j < ITER; j++) {
        int idx = tid + j * NT;
        int r = idx >> 3, c = idx & 7;
        uint32_t off = (uint32_t)(r * 128 + ((c ^ (r & 7)) * 16));
        cp16(dst + off, (const char*)src + (size_t)r * ld * 2 + c * 16);
    }
}

// 1-term chunk: acc += A*B over warp tile (MF*16) x (NF*8), kc=64.
template<int MF, int NF>
__device__ __forceinline__ void compute_single(float (&acc)[MF][NF][4],
                                               uint32_t aA, uint32_t bB,
                                               int wm, int wn, int lane) {
#pragma unroll
    for (int ks = 0; ks < 4; ks++) {
        uint32_t af[MF][4];
#pragma unroll
        for (int mf = 0; mf < MF; mf++) {
            int r = wm + mf * 16 + (lane & 15);
            int c = ks * 2 + (lane >> 4);
            uint32_t off = (uint32_t)(r * 128 + ((c ^ (r & 7)) * 16));
            ldsm_x4(af[mf][0], af[mf][1], af[mf][2], af[mf][3], aA + off);
        }
#pragma unroll
        for (int nfp = 0; nfp < NF / 2; nfp++) {
            int q = lane >> 3;
            int r = wn + (nfp * 2 + (q >> 1)) * 8 + (lane & 7);
            int c = ks * 2 + (q & 1);
            uint32_t off = (uint32_t)(r * 128 + ((c ^ (r & 7)) * 16));
            uint32_t b0, b1, b2, b3;
            ldsm_x4(b0, b1, b2, b3, bB + off);
#pragma unroll
            for (int mf = 0; mf < MF; mf++) {
                mma_f16(acc[mf][2 * nfp],     af[mf], b0, b1);
                mma_f16(acc[mf][2 * nfp + 1], af[mf], b2, b3);
            }
        }
    }
}

// ---------------------------------------------------------------------------
// Fused prep: gates + x fp16 cvt (float4) + W1^T fp16 + W2^T fp16.
//   [0, 4096)       : x cvt (1024 elems per block, float4)
//   [4096, 12288)   : W1 transpose tiles (64 x 16 x 8)
//   [12288, 20480)  : W2 transpose tiles (16 x 64 x 8)
//   [20480]         : gates (first 32 threads)
// ---------------------------------------------------------------------------
__device__ __forceinline__ void transpose_sec(const float* __restrict__ W,
                                              __half* __restrict__ T,
                                              int K, int N, int bx, int by, int bz,
                                              int tx, int ty, float (*s)[33]) {
    int n0 = bx * 32, k0 = by * 32;
    const float* Wp = W + (size_t)bz * K * N;
#pragma unroll
    for (int i = 0; i < 32; i += 8)
        s[ty + i][tx] = Wp[(size_t)(k0 + ty + i) * N + n0 + tx];
    __syncthreads();
#pragma unroll
    for (int i = 0; i < 32; i += 8) {
        int n = n0 + ty + i;
        int k = k0 + tx;
        T[((size_t)bz * N + n) * K + k] = __float2half(s[tx][ty + i]);
    }
}

__global__ void prep_kernel(const float* __restrict__ X,
                            const float* __restrict__ logits,
                            const int*   __restrict__ masks,
                            const float* __restrict__ W1,
                            const float* __restrict__ W2) {
    __shared__ float s[32][33];
    const int blk = blockIdx.x;
    const int tid = threadIdx.x;
    const int tx = tid & 31, ty = tid >> 5;

    if (blk < 4096) {
        // x -> fp16, 4 elems/thread via float4
        size_t i4 = (size_t)blk * 256 + tid;
        float4 v = ((const float4*)X)[i4];
        __half hh[4] = {__float2half(v.x), __float2half(v.y),
                        __float2half(v.z), __float2half(v.w)};
        *(uint2*)(g_x + i4 * 4) = *(uint2*)hh;
    } else if (blk < 12288) {
        int i = blk - 4096;                        // W1: bx<64, by<16, bz<8
        transpose_sec(W1, g_w1t, DM_, FF_, i & 63, (i >> 6) & 15, i >> 10, tx, ty, s);
    } else if (blk < 20480) {
        int i = blk - 12288;                       // W2: bx<16, by<64, bz<8
        transpose_sec(W2, g_w2t, FF_, DM_, i & 15, (i >> 4) & 63, i >> 10, tx, ty, s);
    } else {
        // gates
        int b = tid;
        if (b >= B_) return;
        float p[E_];
        float mx = -1e30f;
#pragma unroll
        for (int i = 0; i < E_; i++) { p[i] = logits[b * E_ + i]; mx = fmaxf(mx, p[i]); }
        float sum = 0.0f;
#pragma unroll
        for (int i = 0; i < E_; i++) { p[i] = expf(p[i] - mx); sum += p[i]; }
        float inv = 1.0f / sum;
#pragma unroll
        for (int i = 0; i < E_; i++) p[i] = (masks[b * E_ + i] == 1) ? p[i] * inv : 0.0f;
        int i1 = 0;
#pragma unroll
        for (int i = 1; i < E_; i++) if (p[i] > p[i1]) i1 = i;
        int i2 = -1;
#pragma unroll
        for (int i = 0; i < E_; i++) {
            if (i == i1) continue;
            if (i2 < 0 || p[i] > p[i2]) i2 = i;
        }
        float denom = p[i1] + p[i2] + 1e-9f;
        g_pair_e[2 * b + 0] = i1;  g_pair_g[2 * b + 0] = p[i1] / denom;
        g_pair_e[2 * b + 1] = i2;  g_pair_g[2 * b + 1] = p[i2] / denom;
    }
}

// ---------------------------------------------------------------------------
// GEMM1 (fp16 1-term): gh[pair] = fp16( g * gelu(x[b] @ W1[e] + b1[e]) )
// BM=128, BN=256, kc=64; stage = A16+B32 = 48KB; 3 stages (144KB), 1 sync/iter.
// 256 threads, warp tile 64x64 (MF=4, NF=8). Grid (8,2,64) = 1024 CTAs.
// ---------------------------------------------------------------------------
#define G1_STAGE  49152u
#define G1_B_O    16384u
#define G1_SMEM   (3 * 49152)

__global__ void __launch_bounds__(256, 1)
gemm1_mma(const float* __restrict__ b1p) {
    extern __shared__ __align__(128) char smem[];
    const int tid = threadIdx.x, lane = tid & 31, wid = tid >> 5;
    const int pair = blockIdx.z;
    const int e = g_pair_e[pair];
    const float g = g_pair_g[pair];
    const int m0 = blockIdx.y * 128, n0 = blockIdx.x * 256;

    const __half* Abase = g_x   + ((size_t)(pair >> 1) * L_ + m0) * DM_;
    const __half* Bbase = g_w1t + ((size_t)e * FF_ + n0) * DM_;

    uint32_t s0 = smem_u32(smem);
    const int wm = (wid >> 2) * 64, wn = (wid & 3) * 64;   // warp tile 64x64

    float acc[4][8][4] = {};
    const int NC = 8;   // 512 / 64

#define G1_LOAD(c, buf) do { int _k = (c) * 64; uint32_t _d = s0 + (buf) * G1_STAGE; \
        load_tile<128, 256>(_d,          Abase + _k, DM_, tid); \
        load_tile<256, 256>(_d + G1_B_O, Bbase + _k, DM_, tid); \
        CP_COMMIT(); } while (0)

    G1_LOAD(0, 0);
    G1_LOAD(1, 1);
    for (int c = 0; c < NC; c++) {
        if (c == NC - 1) asm volatile("cp.async.wait_group 0;" ::: "memory");
        else             asm volatile("cp.async.wait_group 1;" ::: "memory");
        __syncthreads();   // tile c visible; all warps done with buf (c+2)%3 (last read at c-1)
        if (c + 2 < NC) G1_LOAD(c + 2, (uint32_t)((c + 2) % 3));
        uint32_t sb = s0 + (uint32_t)(c % 3) * G1_STAGE;
        compute_single<4, 8>(acc, sb, sb + G1_B_O, wm, wn, lane);
    }
#undef G1_LOAD

    // epilogue: +bias, gelu, *gate, store single fp16
    const float* b1e = b1p + (size_t)e * FF_;
#pragma unroll
    for (int mf = 0; mf < 4; mf++) {
#pragma unroll
        for (int h = 0; h < 2; h++) {
            int r = m0 + wm + mf * 16 + (lane >> 2) + 8 * h;
            __half* rowp = g_gh + ((size_t)pair * L_ + r) * FF_;
#pragma unroll
            for (int nf = 0; nf < 8; nf++) {
                int n = n0 + wn + nf * 8 + (lane & 3) * 2;
                float v0 = acc[mf][nf][2 * h + 0] + __ldg(b1e + n);
                float v1 = acc[mf][nf][2 * h + 1] + __ldg(b1e + n + 1);
                __half hv[2] = {__float2half(gelu_exact(v0) * g),
                                __float2half(gelu_exact(v1) * g)};
                *(uint32_t*)(rowp + n) = *(uint32_t*)hv;
            }
        }
    }
}

// ---------------------------------------------------------------------------
// GEMM2 (fp16 1-term): out[b] = sum_slot gh[b,slot] @ W2[e_slot] + gated bias
// BM=128, BN=64, kc=64; stage = A16+B8 = 24KB; 3 stages (72KB) -> 2 CTAs/SM.
// 256 threads, 8 warps 4x2, warp tile 32x32. Grid (8,2,32) = 512 CTAs.
// Virtual K = 2 slots * 2048 (64 chunks); 1 sync/iter.
// ---------------------------------------------------------------------------
#define H2_STAGE  24576u
#define H2_B_O    16384u
#define H2_SMEM   (3 * 24576)

__global__ void __launch_bounds__(256, 2)
gemm2_mma(const float* __restrict__ b2p, float* __restrict__ out) {
    extern __shared__ __align__(128) char smem[];
    const int tid = threadIdx.x, lane = tid & 31, wid = tid >> 5;
    const int bb = blockIdx.z;
    const int m0 = blockIdx.y * 128, n0 = blockIdx.x * 64;
    const int e0 = g_pair_e[2 * bb + 0], e1 = g_pair_e[2 * bb + 1];
    const float g0 = g_pair_g[2 * bb + 0], g1 = g_pair_g[2 * bb + 1];

    const __half* Ab[2] = {
        g_gh + ((size_t)(2 * bb + 0) * L_ + m0) * FF_,
        g_gh + ((size_t)(2 * bb + 1) * L_ + m0) * FF_
    };
    const __half* Bb[2] = {
        g_w2t + ((size_t)e0 * DM_ + n0) * FF_,
        g_w2t + ((size_t)e1 * DM_ + n0) * FF_
    };

    uint32_t s0 = smem_u32(smem);
    const int wm = (wid >> 1) * 32, wn = (wid & 1) * 32;   // warp tile 32x32

    float acc[2][4][4] = {};
    const int NC = 64;   // 2 slots * (2048/64)

#define G2_LOAD(c, buf) do { \
        int _sl = (c) >> 5; int _k = ((c) & 31) * 64; uint32_t _d = s0 + (buf) * H2_STAGE; \
        load_tile<128, 256>(_d,          Ab[_sl] + _k, FF_, tid); \
        load_tile<64, 256> (_d + H2_B_O, Bb[_sl] + _k, FF_, tid); \
        CP_COMMIT(); } while (0)

    G2_LOAD(0, 0);
    G2_LOAD(1, 1);
    for (int c = 0; c < NC; c++) {
        if (c == NC - 1) asm volatile("cp.async.wait_group 0;" ::: "memory");
        else             asm volatile("cp.async.wait_group 1;" ::: "memory");
        __syncthreads();
        if (c + 2 < NC) G2_LOAD(c + 2, (uint32_t)((c + 2) % 3));
        uint32_t sb = s0 + (uint32_t)(c % 3) * H2_STAGE;
        compute_single<2, 4>(acc, sb, sb + H2_B_O, wm, wn, lane);
    }
#undef G2_LOAD

    const float* b2e0 = b2p + (size_t)e0 * DM_;
    const float* b2e1 = b2p + (size_t)e1 * DM_;
#pragma unroll
    for (int mf = 0; mf < 2; mf++) {
#pragma unroll
        for (int h = 0; h < 2; h++) {
            int r = m0 + wm + mf * 16 + (lane >> 2) + 8 * h;
            float* op = out + ((size_t)bb * L_ + r) * DM_;
#pragma unroll
            for (int nf = 0; nf < 4; nf++) {
                int n = n0 + wn + nf * 8 + (lane & 3) * 2;
                float2 v;
                v.x = acc[mf][nf][2 * h + 0] + g0 * __ldg(b2e0 + n)     + g1 * __ldg(b2e1 + n);
                v.y = acc[mf][nf][2 * h + 1] + g0 * __ldg(b2e0 + n + 1) + g1 * __ldg(b2e1 + n + 1);
                *(float2*)(op + n) = v;
            }
        }
    }
}

// ---------------------------------------------------------------------------
// launch — kernel launches + idempotent attribute opt-ins (no statics)
// ---------------------------------------------------------------------------
extern "C" void kernel_launch(void* const* d_in, const int* in_sizes, int n_in,
                              void* d_out, int out_size) {
    const float* x      = (const float*)d_in[0];
    const float* logits = (const float*)d_in[1];
    const int*   masks  = (const int*)  d_in[2];
    const float* W1     = (const float*)d_in[3];
    const float* b1     = (const float*)d_in[4];
    const float* W2     = (const float*)d_in[5];
    const float* b2     = (const float*)d_in[6];
    float* out = (float*)d_out;

    cudaFuncSetAttribute(gemm1_mma, cudaFuncAttributeMaxDynamicSharedMemorySize, G1_SMEM);
    cudaFuncSetAttribute(gemm2_mma, cudaFuncAttributeMaxDynamicSharedMemorySize, H2_SMEM);

    prep_kernel<<<20481, 256>>>(x, logits, masks, W1, W2);

    gemm1_mma<<<dim3(FF_ / 256, L_ / 128, NPAIR), 256, G1_SMEM>>>(b1);
    gemm2_mma<<<dim3(DM_ / 64, L_ / 128, B_), 256, H2_SMEM>>>(b2, out);
}